// round 2
// baseline (speedup 1.0000x reference)
#include <cuda_runtime.h>
#include <cstdint>

#define NN    3072
#define HH    8
#define FF    64
#define OUTF  512
#define INF_  256
#define BI    24
#define BJ    32

// ---- scratch (device globals; no allocation allowed) ----
__device__ float d_g[NN * OUTF];    // 6 MB: g = x @ W_lin
__device__ float d_sl[NN * HH];
__device__ float d_sr[NN * HH];
__device__ float d_m[NN * HH];      // row max of e
__device__ float d_Cc[NN * HH];     // any0 ? exp(1 - m) : 0

__device__ __forceinline__ void cp16(void* dst_smem, const void* src_gmem) {
    uint32_t s = (uint32_t)__cvta_generic_to_shared(dst_smem);
    asm volatile("cp.async.cg.shared.global [%0], [%1], 16;\n" :: "r"(s), "l"(src_gmem));
}

// ============================================================
// Kernel A: g = x @ W   (3072x256 @ 256x512)
// ============================================================
__global__ void gemm_kernel(const float* __restrict__ x, const float* __restrict__ W) {
    __shared__ float As[32][64];
    __shared__ float Bs[32][64];
    int t = threadIdx.x;
    int m0 = blockIdx.x * 64, n0 = blockIdx.y * 64;
    int tm = (t & 15) * 4, tn = (t >> 4) * 4;
    float acc[4][4] = {};
    for (int k0 = 0; k0 < INF_; k0 += 32) {
        #pragma unroll
        for (int r = 0; r < 2; ++r) {
            int id = t + r * 256;
            int row = id >> 3, kq = (id & 7) * 4;
            float4 v = *(const float4*)(x + (size_t)(m0 + row) * INF_ + k0 + kq);
            As[kq + 0][row] = v.x; As[kq + 1][row] = v.y;
            As[kq + 2][row] = v.z; As[kq + 3][row] = v.w;
            int kk = id >> 4, nq = (id & 15) * 4;
            *(float4*)(&Bs[kk][nq]) = *(const float4*)(W + (size_t)(k0 + kk) * OUTF + n0 + nq);
        }
        __syncthreads();
        #pragma unroll
        for (int k = 0; k < 32; ++k) {
            float4 av = *(float4*)(&As[k][tm]);
            float4 bv = *(float4*)(&Bs[k][tn]);
            float a[4] = {av.x, av.y, av.z, av.w};
            float b[4] = {bv.x, bv.y, bv.z, bv.w};
            #pragma unroll
            for (int i = 0; i < 4; i++)
                #pragma unroll
                for (int j = 0; j < 4; j++) acc[i][j] += a[i] * b[j];
        }
        __syncthreads();
    }
    #pragma unroll
    for (int i = 0; i < 4; i++) {
        float4 v = make_float4(acc[i][0], acc[i][1], acc[i][2], acc[i][3]);
        *(float4*)(d_g + (size_t)(m0 + tm + i) * OUTF + n0 + tn) = v;
    }
}

// ============================================================
// Kernel B: per-(row,head) scores s_l, s_r
// ============================================================
__global__ void score_kernel(const float* __restrict__ aw) {
    int i = blockIdx.x;
    int t = threadIdx.x, h = t >> 5, l = t & 31;
    const float* gr = d_g + (size_t)i * OUTF + h * FF;
    float a0 = gr[l], a1 = gr[l + 32];
    float sl = a0 * aw[l]      + a1 * aw[l + 32];
    float sr = a0 * aw[64 + l] + a1 * aw[96 + l];
    #pragma unroll
    for (int o = 16; o; o >>= 1) {
        sl += __shfl_down_sync(0xffffffffu, sl, o);
        sr += __shfl_down_sync(0xffffffffu, sr, o);
    }
    if (l == 0) { d_sl[i * HH + h] = sl; d_sr[i * HH + h] = sr; }
}

// ============================================================
// Kernel C: per-row adj scan -> m[i,h] (row max of e), C = exp(1-m) if any adj==0
// leaky is monotonic, so max over adj=1 of leaky(sl+sr) = leaky(sl + max_adj sr)
// ============================================================
__global__ void rowc_kernel(const int* __restrict__ adj) {
    int i = blockIdx.x, t = threadIdx.x;
    float mx[8];
    #pragma unroll
    for (int h = 0; h < 8; h++) mx[h] = -3.0e38f;
    int any0 = 0;
    const int* ar = adj + (size_t)i * NN;
    for (int j = t; j < NN; j += 256) {
        if (ar[j]) {
            const float4* p = (const float4*)(d_sr + j * HH);
            float4 v0 = p[0], v1 = p[1];
            mx[0] = fmaxf(mx[0], v0.x); mx[1] = fmaxf(mx[1], v0.y);
            mx[2] = fmaxf(mx[2], v0.z); mx[3] = fmaxf(mx[3], v0.w);
            mx[4] = fmaxf(mx[4], v1.x); mx[5] = fmaxf(mx[5], v1.y);
            mx[6] = fmaxf(mx[6], v1.z); mx[7] = fmaxf(mx[7], v1.w);
        } else any0 = 1;
    }
    __shared__ float wmax[8][8];
    __shared__ int s_any;
    if (t == 0) s_any = 0;
    __syncthreads();
    if (any0) s_any = 1;
    int lane = t & 31, wid = t >> 5;
    #pragma unroll
    for (int h = 0; h < 8; h++) {
        float v = mx[h];
        #pragma unroll
        for (int o = 16; o; o >>= 1) v = fmaxf(v, __shfl_down_sync(0xffffffffu, v, o));
        if (lane == 0) wmax[h][wid] = v;
    }
    __syncthreads();
    if (t < 8) {
        int h = t;
        float mradj = wmax[h][0];
        #pragma unroll
        for (int w = 1; w < 8; w++) mradj = fmaxf(mradj, wmax[h][w]);
        float sl = d_sl[i * HH + h];
        float s  = sl + mradj;
        float lk = fmaxf(s, 0.2f * s);                     // leaky(max over adj=1)
        float m  = s_any ? fmaxf(1.0f, lk) : lk;           // row max of e
        d_m[i * HH + h]  = m;
        d_Cc[i * HH + h] = s_any ? expf(1.0f - m) : 0.0f;
    }
}

// ============================================================
// Kernel D: out[i,h,f] = (1/Z) * sum_j w[i,j,h] * g[j,h,f]
// w = adj ? exp(leaky(sl+sr) - m) : C     (arg <= 0 always -> no overflow)
// ============================================================
constexpr int G_TILE   = BJ * OUTF;             // 16384 floats
constexpr int SM_FLOAT = 2 * G_TILE             // g double-buffer
                       + BI * BJ * HH           // w tile (6144)
                       + 2 * BJ * HH            // sr double (512)
                       + 2 * BI * BJ            // adj double (1536 ints)
                       + BI * HH;               // Z (192)
constexpr int SMEM_BYTES = SM_FLOAT * 4;

__global__ void __launch_bounds__(256, 1) gat_main(const int* __restrict__ adj,
                                                   float* __restrict__ out) {
    extern __shared__ float sm[];
    float* g_s   = sm;                            // [2][16384]
    float* w_s   = sm + 2 * G_TILE;               // [6144]
    float* sr_s  = w_s + BI * BJ * HH;            // [2][256]
    int*   adj_s = (int*)(sr_s + 512);            // [2][768]
    float* Z_s   = (float*)(adj_s + 2 * BI * BJ); // [192]

    int t  = threadIdx.x;
    int i0 = blockIdx.x * BI;

    // w-gen role: thread u<192 owns (il = u/8, h8 = u%8)
    int il = t >> 3, h8 = t & 7;
    bool wgen = (t < BI * HH);
    float slr = 0.f, mr = 0.f, Cr = 0.f, zacc = 0.f;
    if (wgen) {
        int idx = (i0 + il) * HH + h8;
        slr = d_sl[idx]; mr = d_m[idx]; Cr = d_Cc[idx];
    }
    // FMA role: warp = one head, lane -> 2 consecutive f
    int h = t >> 5, c = h * FF + (t & 31) * 2;

    float2 acc[BI];
    #pragma unroll
    for (int i = 0; i < BI; i++) acc[i] = make_float2(0.f, 0.f);

    auto stage = [&](int buf, int tile) {
        int j0 = tile * BJ;
        const float4* gsrc = (const float4*)(d_g + (size_t)j0 * OUTF);
        float4* gdst = (float4*)(g_s + buf * G_TILE);
        #pragma unroll
        for (int k = 0; k < 16; k++) cp16(gdst + k * 256 + t, gsrc + k * 256 + t);
        if (t < 64)
            cp16((float4*)(sr_s + buf * 256) + t, (const float4*)(d_sr + j0 * HH) + t);
        if (t < BI * 8) {   // 24 rows x 8 chunks of 16B
            int r = t >> 3, cc = t & 7;
            cp16((int4*)(adj_s + buf * BI * BJ) + t,
                 (const int4*)(adj + (size_t)(i0 + r) * NN + j0) + cc);
        }
    };

    stage(0, 0);
    asm volatile("cp.async.commit_group;\n");

    const int NT = NN / BJ;  // 96
    for (int tile = 0; tile < NT; ++tile) {
        int cur = tile & 1, nxt = cur ^ 1;
        if (tile + 1 < NT) stage(nxt, tile + 1);
        asm volatile("cp.async.commit_group;\n");
        if (tile + 1 < NT) asm volatile("cp.async.wait_group 1;\n");
        else               asm volatile("cp.async.wait_group 0;\n");
        __syncthreads();

        // ---- phase 1: attention weights for this tile ----
        if (wgen) {
            const int*   ap = adj_s + cur * BI * BJ + il * BJ;
            const float* sp = sr_s + cur * 256;
            #pragma unroll
            for (int j = 0; j < BJ; j++) {
                int a = ap[j];
                float s  = slr + sp[j * HH + h8];
                float lk = fmaxf(s, 0.2f * s);          // leaky_relu
                float w  = a ? __expf(lk - mr) : Cr;    // arg <= 0: safe
                w_s[(il * BJ + j) * HH + h8] = w;
                zacc += w;
            }
        }
        __syncthreads();

        // ---- phase 2: rank-BJ update of out tile (FMA-bound) ----
        const float* gb = g_s + cur * G_TILE;
        #pragma unroll 4
        for (int j = 0; j < BJ; j++) {
            float2 gv = *(const float2*)(gb + j * OUTF + c);
            const float* wp = w_s + j * HH + h;
            #pragma unroll
            for (int i2 = 0; i2 < BI; i2++) {
                float w = wp[i2 * BJ * HH];
                acc[i2].x += w * gv.x;
                acc[i2].y += w * gv.y;
            }
        }
        __syncthreads();
    }

    if (wgen) Z_s[t] = zacc;
    __syncthreads();

    #pragma unroll
    for (int i2 = 0; i2 < BI; i2++) {
        float inv = 1.0f / Z_s[i2 * HH + h];
        float2 o = make_float2(acc[i2].x * inv, acc[i2].y * inv);
        *(float2*)(out + (size_t)(i0 + i2) * OUTF + c) = o;
    }
}

// ============================================================
extern "C" void kernel_launch(void* const* d_in, const int* in_sizes, int n_in,
                              void* d_out, int out_size) {
    const float* x   = (const float*)d_in[0];
    const int*   adj = (const int*)d_in[1];
    const float* W   = (const float*)d_in[2];
    const float* aw  = (const float*)d_in[3];
    float* out = (float*)d_out;

    cudaFuncSetAttribute(gat_main, cudaFuncAttributeMaxDynamicSharedMemorySize, SMEM_BYTES);

    gemm_kernel<<<dim3(NN / 64, OUTF / 64), 256>>>(x, W);
    score_kernel<<<NN, 256>>>(aw);
    rowc_kernel<<<NN, 256>>>(adj);
    gat_main<<<NN / BI, 256, SMEM_BYTES>>>(adj, out);
}

// round 3
// speedup vs baseline: 1.4234x; 1.4234x over previous
#include <cuda_runtime.h>
#include <cstdint>

#define NN    3072
#define HH    8
#define FF    64
#define OUTF  512
#define INF_  256
#define BI    24
#define BJ    32

// ---- scratch (device globals; no allocation allowed) ----
__device__ float d_g[NN * OUTF];    // 6 MB: g = x @ W_lin
__device__ float d_sl[NN * HH];
__device__ float d_sr[NN * HH];
__device__ float d_m[NN * HH];      // row max of e
__device__ float d_Cc[NN * HH];     // any0 ? exp(1 - m) : 0

__device__ __forceinline__ void cp16(void* dst_smem, const void* src_gmem) {
    uint32_t s = (uint32_t)__cvta_generic_to_shared(dst_smem);
    asm volatile("cp.async.cg.shared.global [%0], [%1], 16;\n" :: "r"(s), "l"(src_gmem));
}

// ============================================================
// Kernel A: g = x @ W   (3072x256 @ 256x512)
// ============================================================
__global__ void gemm_kernel(const float* __restrict__ x, const float* __restrict__ W) {
    __shared__ float As[32][64];
    __shared__ float Bs[32][64];
    int t = threadIdx.x;
    int m0 = blockIdx.x * 64, n0 = blockIdx.y * 64;
    int tm = (t & 15) * 4, tn = (t >> 4) * 4;
    float acc[4][4] = {};
    for (int k0 = 0; k0 < INF_; k0 += 32) {
        #pragma unroll
        for (int r = 0; r < 2; ++r) {
            int id = t + r * 256;
            int row = id >> 3, kq = (id & 7) * 4;
            float4 v = *(const float4*)(x + (size_t)(m0 + row) * INF_ + k0 + kq);
            As[kq + 0][row] = v.x; As[kq + 1][row] = v.y;
            As[kq + 2][row] = v.z; As[kq + 3][row] = v.w;
            int kk = id >> 4, nq = (id & 15) * 4;
            *(float4*)(&Bs[kk][nq]) = *(const float4*)(W + (size_t)(k0 + kk) * OUTF + n0 + nq);
        }
        __syncthreads();
        #pragma unroll
        for (int k = 0; k < 32; ++k) {
            float4 av = *(float4*)(&As[k][tm]);
            float4 bv = *(float4*)(&Bs[k][tn]);
            float a[4] = {av.x, av.y, av.z, av.w};
            float b[4] = {bv.x, bv.y, bv.z, bv.w};
            #pragma unroll
            for (int i = 0; i < 4; i++)
                #pragma unroll
                for (int j = 0; j < 4; j++) acc[i][j] += a[i] * b[j];
        }
        __syncthreads();
    }
    #pragma unroll
    for (int i = 0; i < 4; i++) {
        float4 v = make_float4(acc[i][0], acc[i][1], acc[i][2], acc[i][3]);
        *(float4*)(d_g + (size_t)(m0 + tm + i) * OUTF + n0 + tn) = v;
    }
}

// ============================================================
// Kernel B: per-(row,head) scores s_l, s_r
// ============================================================
__global__ void score_kernel(const float* __restrict__ aw) {
    int i = blockIdx.x;
    int t = threadIdx.x, h = t >> 5, l = t & 31;
    const float* gr = d_g + (size_t)i * OUTF + h * FF;
    float a0 = gr[l], a1 = gr[l + 32];
    float sl = a0 * aw[l]      + a1 * aw[l + 32];
    float sr = a0 * aw[64 + l] + a1 * aw[96 + l];
    #pragma unroll
    for (int o = 16; o; o >>= 1) {
        sl += __shfl_down_sync(0xffffffffu, sl, o);
        sr += __shfl_down_sync(0xffffffffu, sr, o);
    }
    if (l == 0) { d_sl[i * HH + h] = sl; d_sr[i * HH + h] = sr; }
}

// ============================================================
// Kernel C: per-row adj scan -> m[i,h], C = exp(1-m) if any adj==0
// ============================================================
__global__ void rowc_kernel(const int* __restrict__ adj) {
    int i = blockIdx.x, t = threadIdx.x;
    float mx[8];
    #pragma unroll
    for (int h = 0; h < 8; h++) mx[h] = -3.0e38f;
    int any0 = 0;
    const int* ar = adj + (size_t)i * NN;
    for (int j = t; j < NN; j += 256) {
        if (ar[j]) {
            const float4* p = (const float4*)(d_sr + j * HH);
            float4 v0 = p[0], v1 = p[1];
            mx[0] = fmaxf(mx[0], v0.x); mx[1] = fmaxf(mx[1], v0.y);
            mx[2] = fmaxf(mx[2], v0.z); mx[3] = fmaxf(mx[3], v0.w);
            mx[4] = fmaxf(mx[4], v1.x); mx[5] = fmaxf(mx[5], v1.y);
            mx[6] = fmaxf(mx[6], v1.z); mx[7] = fmaxf(mx[7], v1.w);
        } else any0 = 1;
    }
    __shared__ float wmax[8][8];
    __shared__ int s_any;
    if (t == 0) s_any = 0;
    __syncthreads();
    if (any0) s_any = 1;
    int lane = t & 31, wid = t >> 5;
    #pragma unroll
    for (int h = 0; h < 8; h++) {
        float v = mx[h];
        #pragma unroll
        for (int o = 16; o; o >>= 1) v = fmaxf(v, __shfl_down_sync(0xffffffffu, v, o));
        if (lane == 0) wmax[h][wid] = v;
    }
    __syncthreads();
    if (t < 8) {
        int h = t;
        float mradj = wmax[h][0];
        #pragma unroll
        for (int w = 1; w < 8; w++) mradj = fmaxf(mradj, wmax[h][w]);
        float sl = d_sl[i * HH + h];
        float s  = sl + mradj;
        float lk = fmaxf(s, 0.2f * s);
        float m  = s_any ? fmaxf(1.0f, lk) : lk;
        d_m[i * HH + h]  = m;
        d_Cc[i * HH + h] = s_any ? expf(1.0f - m) : 0.0f;
    }
}

// ============================================================
// Kernel D: out[i,h,f] = (1/Z) * sum_j w[i,j,h] * g[j,h,f]
// 512 threads: j-range split across two warp groups (private acc, merged at end)
// w_s layout [j][h][i] -> float4 w loads in the FMA loop
// ============================================================
constexpr int G_TILE   = BJ * OUTF;             // 16384 floats
constexpr int W_TILE   = BJ * HH * BI;          // 6144 floats
constexpr int SM_FLOAT = 2 * G_TILE             // g double-buffer (131072 B)
                       + W_TILE                 // w tile
                       + 2 * BJ * HH            // sr double (512)
                       + 2 * BI * BJ            // adj double (1536 ints)
                       + 2 * BI * HH;           // Z partials (384)
constexpr int SMEM_BYTES = SM_FLOAT * 4;

__global__ void __launch_bounds__(512, 1) gat_main(const int* __restrict__ adj,
                                                   float* __restrict__ out) {
    extern __shared__ float sm[];
    float* g_s   = sm;                            // [2][16384]
    float* w_s   = sm + 2 * G_TILE;               // [32][8][24]
    float* sr_s  = w_s + W_TILE;                  // [2][256]
    int*   adj_s = (int*)(sr_s + 512);            // [2][768]
    float* Z_s   = (float*)(adj_s + 2 * BI * BJ); // [2][192]

    int t  = threadIdx.x;
    int i0 = blockIdx.x * BI;

    // ---- w-gen role: t<384, pair = t>>1 owns (il, h8), jh = t&1 owns 16 j's
    int pair = t >> 1, jh_w = t & 1;
    int il = pair / 8, h8 = pair & 7;
    bool wgen = (t < 2 * BI * HH);
    float slr = 0.f, mr = 0.f, Cr = 0.f, zacc = 0.f;
    if (wgen) {
        int idx = (i0 + il) * HH + h8;
        slr = d_sl[idx]; mr = d_m[idx]; Cr = d_Cc[idx];
    }

    // ---- FMA role: warp (t&255)>>5 = head, lane -> 2 f's; t>>8 = j-half
    int h = (t & 255) >> 5, c = h * FF + (t & 31) * 2;
    int jbase = (t >> 8) * 16;

    float2 acc[BI];
    #pragma unroll
    for (int i = 0; i < BI; i++) acc[i] = make_float2(0.f, 0.f);

    auto stage = [&](int buf, int tile) {
        int j0 = tile * BJ;
        const float4* gsrc = (const float4*)(d_g + (size_t)j0 * OUTF);
        float4* gdst = (float4*)(g_s + buf * G_TILE);
        #pragma unroll
        for (int k = 0; k < 8; k++) cp16(gdst + k * 512 + t, gsrc + k * 512 + t);
        if (t < 64)
            cp16((float4*)(sr_s + buf * 256) + t, (const float4*)(d_sr + j0 * HH) + t);
        if (t < BI * 8) {
            int r = t >> 3, cc = t & 7;
            cp16((int4*)(adj_s + buf * BI * BJ) + t,
                 (const int4*)(adj + (size_t)(i0 + r) * NN + j0) + cc);
        }
    };

    stage(0, 0);
    asm volatile("cp.async.commit_group;\n");

    const int NT = NN / BJ;  // 96
    for (int tile = 0; tile < NT; ++tile) {
        int cur = tile & 1, nxt = cur ^ 1;
        if (tile + 1 < NT) stage(nxt, tile + 1);
        asm volatile("cp.async.commit_group;\n");
        if (tile + 1 < NT) asm volatile("cp.async.wait_group 1;\n");
        else               asm volatile("cp.async.wait_group 0;\n");
        __syncthreads();

        // ---- phase 1: attention weights; w_s[j][h][i] ----
        if (wgen) {
            const int*   ap = adj_s + cur * BI * BJ + il * BJ;
            const float* sp = sr_s + cur * 256;
            #pragma unroll 4
            for (int jj = 0; jj < 16; jj++) {
                int j = jh_w * 16 + jj;
                int a = ap[j];
                float s  = slr + sp[j * HH + h8];
                float lk = fmaxf(s, 0.2f * s);
                float w  = a ? __expf(lk - mr) : Cr;
                w_s[(j * HH + h8) * BI + il] = w;
                zacc += w;
            }
        }
        __syncthreads();

        // ---- phase 2: rank-16 update per warp-group (FMA-bound) ----
        const float* gb = g_s + cur * G_TILE;
        #pragma unroll 2
        for (int jj = 0; jj < 16; jj++) {
            int j = jbase + jj;
            float2 gv = *(const float2*)(gb + j * OUTF + c);
            const float4* wp = (const float4*)(w_s + (j * HH + h) * BI);
            float4 w0 = wp[0], w1 = wp[1], w2 = wp[2];
            float4 w3 = wp[3], w4 = wp[4], w5 = wp[5];
            float wv[24] = {w0.x,w0.y,w0.z,w0.w, w1.x,w1.y,w1.z,w1.w,
                            w2.x,w2.y,w2.z,w2.w, w3.x,w3.y,w3.z,w3.w,
                            w4.x,w4.y,w4.z,w4.w, w5.x,w5.y,w5.z,w5.w};
            #pragma unroll
            for (int i2 = 0; i2 < BI; i2++) {
                acc[i2].x += wv[i2] * gv.x;
                acc[i2].y += wv[i2] * gv.y;
            }
        }
        __syncthreads();
    }

    // ---- epilogue: merge the two j-half accumulators, normalize ----
    if (wgen) Z_s[jh_w * 192 + pair] = zacc;
    float* red = g_s;   // reuse
    if (t >= 256) {
        #pragma unroll
        for (int i2 = 0; i2 < BI; i2++)
            *(float2*)(red + i2 * 512 + c) = acc[i2];
    }
    __syncthreads();
    if (t < 256) {
        #pragma unroll
        for (int i2 = 0; i2 < BI; i2++) {
            float2 o = *(const float2*)(red + i2 * 512 + c);
            float z = Z_s[i2 * 8 + h] + Z_s[192 + i2 * 8 + h];
            float inv = 1.0f / z;
            float2 r = make_float2((acc[i2].x + o.x) * inv,
                                   (acc[i2].y + o.y) * inv);
            *(float2*)(out + (size_t)(i0 + i2) * OUTF + c) = r;
        }
    }
}

// ============================================================
extern "C" void kernel_launch(void* const* d_in, const int* in_sizes, int n_in,
                              void* d_out, int out_size) {
    const float* x   = (const float*)d_in[0];
    const int*   adj = (const int*)d_in[1];
    const float* W   = (const float*)d_in[2];
    const float* aw  = (const float*)d_in[3];
    float* out = (float*)d_out;

    cudaFuncSetAttribute(gat_main, cudaFuncAttributeMaxDynamicSharedMemorySize, SMEM_BYTES);

    gemm_kernel<<<dim3(NN / 64, OUTF / 64), 256>>>(x, W);
    score_kernel<<<NN, 256>>>(aw);
    rowc_kernel<<<NN, 256>>>(adj);
    gat_main<<<NN / BI, 512, SMEM_BYTES>>>(adj, out);
}

// round 5
// speedup vs baseline: 4.2007x; 2.9512x over previous
#include <cuda_runtime.h>
#include <cuda_fp16.h>
#include <cstdint>

#define NN    3072
#define HH    8
#define FF    64
#define OUTF  512
#define INF_  256
#define KT    64
#define NT    (NN / KT)     // 48
#define MI    96            // i rows per CTA
#define NW    (NN / 32)     // 96 adj bitmask words per row

// ---- scratch (device globals) ----
__device__ float d_g[NN * OUTF];
__device__ float d_sl[NN * HH];
__device__ float d_sr[NN * HH];
__device__ float d_m[NN * HH];
__device__ float d_Cc[NN * HH];
__device__ uint32_t d_adjbits[NN * NW];
__device__ __half d_gthi[HH * FF * NN];   // gT hi split, j-permuted: [h][f][j']
__device__ __half d_gtlo[HH * FF * NN];   // gT lo split

// j-permutation within 16-group: position p holds actual kappa(p)
#define KTAB(pp) (2 * ((pp) >> 2) + (((pp) & 2) ? 8 : 0) + ((pp) & 1))

// ---------------- helpers ----------------
__device__ __forceinline__ uint32_t smem_u32(const void* p) {
    uint32_t a;
    asm("{ .reg .u64 t; cvta.to.shared.u64 t, %1; cvt.u32.u64 %0, t; }" : "=r"(a) : "l"(p));
    return a;
}
__device__ __forceinline__ void cp16(void* dst, const void* src) {
    asm volatile("cp.async.cg.shared.global [%0], [%1], 16;\n" :: "r"(smem_u32(dst)), "l"(src));
}
__device__ __forceinline__ void cp4(void* dst, const void* src) {
    asm volatile("cp.async.ca.shared.global [%0], [%1], 4;\n" :: "r"(smem_u32(dst)), "l"(src));
}
#define CP_COMMIT() asm volatile("cp.async.commit_group;\n")
#define CP_WAIT(n)  asm volatile("cp.async.wait_group %0;\n" :: "n"(n))

__device__ __forceinline__ void mma16816(float* d, const uint32_t* a,
                                         uint32_t b0, uint32_t b1) {
    asm volatile(
        "mma.sync.aligned.m16n8k16.row.col.f32.f16.f16.f32 "
        "{%0,%1,%2,%3}, {%4,%5,%6,%7}, {%8,%9}, {%0,%1,%2,%3};"
        : "+f"(d[0]), "+f"(d[1]), "+f"(d[2]), "+f"(d[3])
        : "r"(a[0]), "r"(a[1]), "r"(a[2]), "r"(a[3]), "r"(b0), "r"(b1));
}
__device__ __forceinline__ uint32_t ph2(float lo, float hi) {
    __half2 h = __floats2half2_rn(lo, hi);
    return *(uint32_t*)&h;
}

// ============================================================
// Kernel A: g = x @ W (fp32 SIMT, exact)
// ============================================================
__global__ void gemm_kernel(const float* __restrict__ x, const float* __restrict__ W) {
    __shared__ float As[32][64];
    __shared__ float Bs[32][64];
    int t = threadIdx.x;
    int m0 = blockIdx.x * 64, n0 = blockIdx.y * 64;
    int tm = (t & 15) * 4, tn = (t >> 4) * 4;
    float acc[4][4] = {};
    for (int k0 = 0; k0 < INF_; k0 += 32) {
        #pragma unroll
        for (int r = 0; r < 2; ++r) {
            int id = t + r * 256;
            int row = id >> 3, kq = (id & 7) * 4;
            float4 v = *(const float4*)(x + (size_t)(m0 + row) * INF_ + k0 + kq);
            As[kq + 0][row] = v.x; As[kq + 1][row] = v.y;
            As[kq + 2][row] = v.z; As[kq + 3][row] = v.w;
            int kk = id >> 4, nq = (id & 15) * 4;
            *(float4*)(&Bs[kk][nq]) = *(const float4*)(W + (size_t)(k0 + kk) * OUTF + n0 + nq);
        }
        __syncthreads();
        #pragma unroll
        for (int k = 0; k < 32; ++k) {
            float4 av = *(float4*)(&As[k][tm]);
            float4 bv = *(float4*)(&Bs[k][tn]);
            float a[4] = {av.x, av.y, av.z, av.w};
            float b[4] = {bv.x, bv.y, bv.z, bv.w};
            #pragma unroll
            for (int i = 0; i < 4; i++)
                #pragma unroll
                for (int j = 0; j < 4; j++) acc[i][j] += a[i] * b[j];
        }
        __syncthreads();
    }
    #pragma unroll
    for (int i = 0; i < 4; i++) {
        float4 v = make_float4(acc[i][0], acc[i][1], acc[i][2], acc[i][3]);
        *(float4*)(d_g + (size_t)(m0 + tm + i) * OUTF + n0 + tn) = v;
    }
}

// ============================================================
// Kernel B: scores s_l, s_r
// ============================================================
__global__ void score_kernel(const float* __restrict__ aw) {
    int i = blockIdx.x;
    int t = threadIdx.x, h = t >> 5, l = t & 31;
    const float* gr = d_g + (size_t)i * OUTF + h * FF;
    float a0 = gr[l], a1 = gr[l + 32];
    float sl = a0 * aw[l]      + a1 * aw[l + 32];
    float sr = a0 * aw[64 + l] + a1 * aw[96 + l];
    #pragma unroll
    for (int o = 16; o; o >>= 1) {
        sl += __shfl_down_sync(0xffffffffu, sl, o);
        sr += __shfl_down_sync(0xffffffffu, sr, o);
    }
    if (l == 0) { d_sl[i * HH + h] = sl; d_sr[i * HH + h] = sr; }
}

// ============================================================
// Kernel C: per-row adj scan -> m[i,h], C; packs adj to bits
// ============================================================
__global__ void rowc_kernel(const int* __restrict__ adj) {
    int i = blockIdx.x, t = threadIdx.x;
    float mx[8];
    #pragma unroll
    for (int h = 0; h < 8; h++) mx[h] = -3.0e38f;
    int any0 = 0;
    const int* ar = adj + (size_t)i * NN;
    for (int j = t; j < NN; j += 256) {
        int a = ar[j];
        uint32_t bal = __ballot_sync(0xffffffffu, a != 0);
        if ((t & 31) == 0) d_adjbits[i * NW + (j >> 5)] = bal;
        if (a) {
            const float4* p = (const float4*)(d_sr + j * HH);
            float4 v0 = p[0], v1 = p[1];
            mx[0] = fmaxf(mx[0], v0.x); mx[1] = fmaxf(mx[1], v0.y);
            mx[2] = fmaxf(mx[2], v0.z); mx[3] = fmaxf(mx[3], v0.w);
            mx[4] = fmaxf(mx[4], v1.x); mx[5] = fmaxf(mx[5], v1.y);
            mx[6] = fmaxf(mx[6], v1.z); mx[7] = fmaxf(mx[7], v1.w);
        } else any0 = 1;
    }
    __shared__ float wmax[8][8];
    __shared__ int s_any;
    if (t == 0) s_any = 0;
    __syncthreads();
    if (any0) s_any = 1;
    int lane = t & 31, wid = t >> 5;
    #pragma unroll
    for (int h = 0; h < 8; h++) {
        float v = mx[h];
        #pragma unroll
        for (int o = 16; o; o >>= 1) v = fmaxf(v, __shfl_down_sync(0xffffffffu, v, o));
        if (lane == 0) wmax[h][wid] = v;
    }
    __syncthreads();
    if (t < 8) {
        int h = t;
        float mradj = wmax[h][0];
        #pragma unroll
        for (int w = 1; w < 8; w++) mradj = fmaxf(mradj, wmax[h][w]);
        float sl = d_sl[i * HH + h];
        float s  = sl + mradj;
        float lk = fmaxf(s, 0.2f * s);
        float m  = s_any ? fmaxf(1.0f, lk) : lk;
        d_m[i * HH + h]  = m;
        d_Cc[i * HH + h] = s_any ? expf(1.0f - m) : 0.0f;
    }
}

// ============================================================
// Kernel E: gT split to fp16 hi/lo with j-permutation
// d_g[j][h*64+f] -> d_gthi/lo[h][f][j'] where j' = perm(j)
// ============================================================
__global__ void gsplit_kernel() {
    __shared__ float s[64][132];
    int t = threadIdx.x;
    int j0 = blockIdx.x * 128, h = blockIdx.y;
    #pragma unroll
    for (int k = 0; k < 16; k++) {
        int idx = t + k * 256;
        int j = idx >> 5, fq = (idx & 31) * 2;
        float2 v = *(const float2*)(d_g + (size_t)(j0 + j) * OUTF + h * FF + fq);
        s[fq][j] = v.x; s[fq + 1][j] = v.y;
    }
    __syncthreads();
    #pragma unroll
    for (int k = 0; k < 4; k++) {
        int idx = t + k * 256;
        int f = idx >> 4, jc = (idx & 15) * 8;   // 8 output positions
        uint32_t hw[4], lw[4];
        #pragma unroll
        for (int qq = 0; qq < 4; qq++) {
            float v[2];
            #pragma unroll
            for (int e = 0; e < 2; e++) {
                int p = jc + qq * 2 + e;
                int grp = p & ~15, pp = p & 15;
                v[e] = s[f][grp + KTAB(pp)];
            }
            __half h0 = __float2half_rn(v[0]), h1 = __float2half_rn(v[1]);
            float r0 = v[0] - __half2float(h0), r1 = v[1] - __half2float(h1);
            __half l0 = __float2half_rn(r0), l1 = __float2half_rn(r1);
            hw[qq] = ((uint32_t)__half_as_ushort(h1) << 16) | __half_as_ushort(h0);
            lw[qq] = ((uint32_t)__half_as_ushort(l1) << 16) | __half_as_ushort(l0);
        }
        size_t off = ((size_t)h * FF + f) * NN + j0 + jc;
        *(uint4*)(d_gthi + off) = make_uint4(hw[0], hw[1], hw[2], hw[3]);
        *(uint4*)(d_gtlo + off) = make_uint4(lw[0], lw[1], lw[2], lw[3]);
    }
}

// ============================================================
// Kernel F: HMMA main. 128 CTAs = 32 i-tiles(96) x 4 head-pairs, 384 thr.
// Warp w: head hl = w/6, m-tile mt = w%6 (16 i-rows). D in regs (fp32).
// Per 64-j tile: w-gen into A frags (fp16), 2-pass mma vs g_hi/g_lo.
// ============================================================
constexpr int BSM_HALVES = 2 * 4 * 64 * 80;        // [buf][hl*2+sp][f][80]
constexpr int OFF_SR = BSM_HALVES * 2;             // 81920 B
constexpr int OFF_Z  = OFF_SR + 2 * 2 * 64 * 4;    // +1024
constexpr int SMEM_TC = OFF_Z + MI * 2 * 4;        // +768 = 83712

__global__ void __launch_bounds__(384, 1) gat_tc(float* __restrict__ out) {
    extern __shared__ char smem[];
    __half* Bsm = (__half*)smem;
    float* sr_s = (float*)(smem + OFF_SR);   // [buf][head][64]
    float* Z_s  = (float*)(smem + OFF_Z);    // [96][2]

    int t = threadIdx.x, lane = t & 31, w = t >> 5;
    int hp = blockIdx.x & 3;
    int i0 = (blockIdx.x >> 2) * MI;
    int hl = (w >= 6), mt = (w >= 6) ? w - 6 : w;
    int gid = lane >> 2, tig = lane & 3;
    int r0 = mt * 16 + gid;                  // local rows r0, r0+8

    int gi0 = (i0 + r0) * HH + hp * 2 + hl;
    float sl0 = d_sl[gi0], m0v = d_m[gi0], C0 = d_Cc[gi0];
    int gi1 = gi0 + 8 * HH;
    float sl1 = d_sl[gi1], m1v = d_m[gi1], C1 = d_Cc[gi1];

    const uint32_t* ab0 = d_adjbits + (size_t)(i0 + r0) * NW;
    const uint32_t* ab1 = ab0 + 8 * NW;

    float d[8][4] = {};
    float zA = 0.f, zB = 0.f;

    auto stage = [&](int buf, int jt) {
        int j0 = jt * KT;
        #pragma unroll
        for (int k = 0; k < 6; k++) {
            int idx = t + k * 384;
            if (idx < 2048) {
                int reg = idx >> 9;              // shl*2 + sp
                int shl = reg >> 1, sp = reg & 1;
                int rc = idx & 511;
                int f = rc >> 3, c = rc & 7;
                const __half* src = (sp ? d_gtlo : d_gthi)
                    + ((size_t)(hp * 2 + shl) * FF + f) * NN + j0 + c * 8;
                cp16(Bsm + (size_t)((buf * 4 + reg) * 64 + f) * 80 + c * 8, src);
            }
        }
        if (t < 128) {
            int head = t >> 6, p = t & 63;
            int j = j0 + (p & ~15) + KTAB(p & 15);
            cp4(&sr_s[(buf * 2 + head) * 64 + p],
                d_sr + (size_t)j * HH + hp * 2 + head);
        }
    };

    stage(0, 0);
    CP_COMMIT();

    for (int jt = 0; jt < NT; ++jt) {
        int buf = jt & 1, nb = buf ^ 1;
        if (jt + 1 < NT) { stage(nb, jt + 1); CP_COMMIT(); CP_WAIT(1); }
        else             { CP_WAIT(0); }
        __syncthreads();

        // adj bits for this CTA-row pair
        uint2 bw0 = *(const uint2*)(ab0 + jt * 2);
        uint2 bw1 = *(const uint2*)(ab1 + jt * 2);
        uint64_t bits0 = (uint64_t)bw0.x | ((uint64_t)bw0.y << 32);
        uint64_t bits1 = (uint64_t)bw1.x | ((uint64_t)bw1.y << 32);

        // ---- A frags (w-gen) for 4 ksteps ----
        uint32_t A[4][4];
        const float* srh = sr_s + (buf * 2 + hl) * 64;
        #pragma unroll
        for (int s = 0; s < 4; s++) {
            float4 sv = *(const float4*)(srh + s * 16 + 4 * tig);
            int jb = s * 16 + 2 * tig;   // kappa indices: jb, jb+1, jb+8, jb+9
            float q0 = sl0 + sv.x, q1 = sl0 + sv.y, q2 = sl0 + sv.z, q3 = sl0 + sv.w;
            float e00 = __expf(fmaxf(q0, 0.2f * q0) - m0v);
            float e01 = __expf(fmaxf(q1, 0.2f * q1) - m0v);
            float e02 = __expf(fmaxf(q2, 0.2f * q2) - m0v);
            float e03 = __expf(fmaxf(q3, 0.2f * q3) - m0v);
            float w00 = ((bits0 >> jb) & 1)       ? e00 : C0;
            float w01 = ((bits0 >> (jb + 1)) & 1) ? e01 : C0;
            float w02 = ((bits0 >> (jb + 8)) & 1) ? e02 : C0;
            float w03 = ((bits0 >> (jb + 9)) & 1) ? e03 : C0;
            float p0 = sl1 + sv.x, p1 = sl1 + sv.y, p2 = sl1 + sv.z, p3 = sl1 + sv.w;
            float e10 = __expf(fmaxf(p0, 0.2f * p0) - m1v);
            float e11 = __expf(fmaxf(p1, 0.2f * p1) - m1v);
            float e12 = __expf(fmaxf(p2, 0.2f * p2) - m1v);
            float e13 = __expf(fmaxf(p3, 0.2f * p3) - m1v);
            float w10 = ((bits1 >> jb) & 1)       ? e10 : C1;
            float w11 = ((bits1 >> (jb + 1)) & 1) ? e11 : C1;
            float w12 = ((bits1 >> (jb + 8)) & 1) ? e12 : C1;
            float w13 = ((bits1 >> (jb + 9)) & 1) ? e13 : C1;
            zA += (w00 + w01) + (w02 + w03);
            zB += (w10 + w11) + (w12 + w13);
            A[s][0] = ph2(w00, w01);   // row gid,   k-low
            A[s][1] = ph2(w10, w11);   // row gid+8, k-low
            A[s][2] = ph2(w02, w03);   // row gid,   k-high
            A[s][3] = ph2(w12, w13);   // row gid+8, k-high
        }

        // ---- 2-pass MMA (g_hi, g_lo) ----
        #pragma unroll
        for (int sp = 0; sp < 2; sp++) {
            const __half* bb = Bsm + (size_t)((buf * 4 + hl * 2 + sp) * 64) * 80;
            #pragma unroll
            for (int s = 0; s < 4; s++) {
                #pragma unroll
                for (int nt = 0; nt < 8; nt++) {
                    uint2 b = *(const uint2*)(bb + (nt * 8 + gid) * 80 + s * 16 + 4 * tig);
                    mma16816(d[nt], A[s], b.x, b.y);
                }
            }
        }
        __syncthreads();
    }

    // ---- Z reduce (over tig quad) + write ----
    zA += __shfl_xor_sync(0xffffffffu, zA, 1);
    zA += __shfl_xor_sync(0xffffffffu, zA, 2);
    zB += __shfl_xor_sync(0xffffffffu, zB, 1);
    zB += __shfl_xor_sync(0xffffffffu, zB, 2);
    if (tig == 0) {
        Z_s[r0 * 2 + hl] = zA;
        Z_s[(r0 + 8) * 2 + hl] = zB;
    }
    __syncthreads();

    float inv0 = 1.0f / Z_s[r0 * 2 + hl];
    float inv1 = 1.0f / Z_s[(r0 + 8) * 2 + hl];
    int col0 = (hp * 2 + hl) * FF + 2 * tig;
    float* o0 = out + (size_t)(i0 + r0) * OUTF + col0;
    float* o1 = out + (size_t)(i0 + r0 + 8) * OUTF + col0;
    #pragma unroll
    for (int nt = 0; nt < 8; nt++) {
        *(float2*)(o0 + nt * 8) = make_float2(d[nt][0] * inv0, d[nt][1] * inv0);
        *(float2*)(o1 + nt * 8) = make_float2(d[nt][2] * inv1, d[nt][3] * inv1);
    }
}

// ============================================================
extern "C" void kernel_launch(void* const* d_in, const int* in_sizes, int n_in,
                              void* d_out, int out_size) {
    const float* x   = (const float*)d_in[0];
    const int*   adj = (const int*)d_in[1];
    const float* W   = (const float*)d_in[2];
    const float* aw  = (const float*)d_in[3];
    float* out = (float*)d_out;

    cudaFuncSetAttribute(gat_tc, cudaFuncAttributeMaxDynamicSharedMemorySize, SMEM_TC);

    gemm_kernel<<<dim3(NN / 64, OUTF / 64), 256>>>(x, W);
    score_kernel<<<NN, 256>>>(aw);
    rowc_kernel<<<NN, 256>>>(adj);
    gsplit_kernel<<<dim3(NN / 128, HH), 256>>>();
    gat_tc<<<(NN / MI) * 4, 384, SMEM_TC>>>(out);
}

// round 6
// speedup vs baseline: 4.5368x; 1.0800x over previous
#include <cuda_runtime.h>
#include <cuda_fp16.h>
#include <cstdint>

#define NN    3072
#define HH    8
#define FF    64
#define OUTF  512
#define INF_  256
#define KT    64
#define NT    (NN / KT)     // 48
#define MI    96            // i rows per CTA in gat_tc
#define NW    (NN / 32)     // 96 adj bitmask words per row

// ---- scratch (device globals) ----
__device__ float d_g[NN * OUTF];
__device__ float d_sl[NN * HH];
__device__ float d_sr[NN * HH];
__device__ float d_m[NN * HH];
__device__ float d_Cc[NN * HH];
__device__ uint32_t d_adjbits[NN * NW];
__device__ __half d_gthi[HH * FF * NN];   // gT hi split, j-permuted: [h][f][j']
__device__ __half d_gtlo[HH * FF * NN];   // gT lo split
__device__ __half d_xphi[NN * INF_];      // x split hi, k-permuted
__device__ __half d_xplo[NN * INF_];
__device__ __half d_wthi[OUTF * INF_];    // W^T split hi, k-permuted: [n][k']
__device__ __half d_wtlo[OUTF * INF_];

// permutation within 16-group: position p holds actual k = KTAB(p)
#define KTAB(pp) (2 * ((pp) >> 2) + (((pp) & 2) ? 8 : 0) + ((pp) & 1))

// ---------------- helpers ----------------
__device__ __forceinline__ uint32_t smem_u32(const void* p) {
    uint32_t a;
    asm("{ .reg .u64 t; cvta.to.shared.u64 t, %1; cvt.u32.u64 %0, t; }" : "=r"(a) : "l"(p));
    return a;
}
__device__ __forceinline__ void cp16(void* dst, const void* src) {
    asm volatile("cp.async.cg.shared.global [%0], [%1], 16;\n" :: "r"(smem_u32(dst)), "l"(src));
}
__device__ __forceinline__ void cp4(void* dst, const void* src) {
    asm volatile("cp.async.ca.shared.global [%0], [%1], 4;\n" :: "r"(smem_u32(dst)), "l"(src));
}
#define CP_COMMIT() asm volatile("cp.async.commit_group;\n")
#define CP_WAIT(n)  asm volatile("cp.async.wait_group %0;\n" :: "n"(n))

__device__ __forceinline__ void mma16816(float* d, const uint32_t* a,
                                         uint32_t b0, uint32_t b1) {
    asm volatile(
        "mma.sync.aligned.m16n8k16.row.col.f32.f16.f16.f32 "
        "{%0,%1,%2,%3}, {%4,%5,%6,%7}, {%8,%9}, {%0,%1,%2,%3};"
        : "+f"(d[0]), "+f"(d[1]), "+f"(d[2]), "+f"(d[3])
        : "r"(a[0]), "r"(a[1]), "r"(a[2]), "r"(a[3]), "r"(b0), "r"(b1));
}
__device__ __forceinline__ uint32_t ph2(float lo, float hi) {
    __half2 h = __floats2half2_rn(lo, hi);
    return *(uint32_t*)&h;
}
__device__ __forceinline__ void split16(const float* v_strided, int stride,
                                        uint4* hi2, uint4* lo2) {
    // reads 16 floats at positions KTAB(p)*stride, packs to 2x uint4 hi + 2x uint4 lo
    uint32_t hw[8], lw[8];
    #pragma unroll
    for (int q = 0; q < 8; q++) {
        float v0 = v_strided[KTAB(2 * q) * stride];
        float v1 = v_strided[KTAB(2 * q + 1) * stride];
        __half h0 = __float2half_rn(v0), h1 = __float2half_rn(v1);
        float r0 = v0 - __half2float(h0), r1 = v1 - __half2float(h1);
        __half l0 = __float2half_rn(r0), l1 = __float2half_rn(r1);
        hw[q] = ((uint32_t)__half_as_ushort(h1) << 16) | __half_as_ushort(h0);
        lw[q] = ((uint32_t)__half_as_ushort(l1) << 16) | __half_as_ushort(l0);
    }
    hi2[0] = make_uint4(hw[0], hw[1], hw[2], hw[3]);
    hi2[1] = make_uint4(hw[4], hw[5], hw[6], hw[7]);
    lo2[0] = make_uint4(lw[0], lw[1], lw[2], lw[3]);
    lo2[1] = make_uint4(lw[4], lw[5], lw[6], lw[7]);
}

// ============================================================
// Kernel P1: x -> split fp16 hi/lo, k-permuted. CTA: 16 rows x 256 k.
// ============================================================
__global__ void xsplit_kernel(const float* __restrict__ x) {
    __shared__ float s[16][257];
    int t = threadIdx.x, r0 = blockIdx.x * 16;
    #pragma unroll
    for (int q = 0; q < 4; q++) {
        int idx = t + q * 256;
        int r = idx >> 6, c4 = (idx & 63) * 4;
        float4 v = *(const float4*)(x + (size_t)(r0 + r) * INF_ + c4);
        s[r][c4] = v.x; s[r][c4 + 1] = v.y; s[r][c4 + 2] = v.z; s[r][c4 + 3] = v.w;
    }
    __syncthreads();
    int r = t >> 4, grp = (t & 15) * 16;
    uint4 hi2[2], lo2[2];
    split16(&s[r][grp], 1, hi2, lo2);
    uint4* dh = (uint4*)(d_xphi + (size_t)(r0 + r) * INF_ + grp);
    uint4* dl = (uint4*)(d_xplo + (size_t)(r0 + r) * INF_ + grp);
    dh[0] = hi2[0]; dh[1] = hi2[1];
    dl[0] = lo2[0]; dl[1] = lo2[1];
}

// ============================================================
// Kernel P2: W[k][n] -> WT split fp16 hi/lo [n][k'], k-permuted.
// grid (4 kt, 8 nt): tile 64k x 64n
// ============================================================
__global__ void wsplit_kernel(const float* __restrict__ W) {
    __shared__ float s[64][65];
    int t = threadIdx.x;
    int k0 = blockIdx.x * 64, n0 = blockIdx.y * 64;
    #pragma unroll
    for (int q = 0; q < 4; q++) {
        int idx = t + q * 256;
        int k = idx >> 4, n4 = (idx & 15) * 4;
        float4 v = *(const float4*)(W + (size_t)(k0 + k) * OUTF + n0 + n4);
        s[k][n4] = v.x; s[k][n4 + 1] = v.y; s[k][n4 + 2] = v.z; s[k][n4 + 3] = v.w;
    }
    __syncthreads();
    int n = t >> 2, grp = (t & 3) * 16;
    uint4 hi2[2], lo2[2];
    split16(&s[grp][n], 65, hi2, lo2);
    uint4* dh = (uint4*)(d_wthi + (size_t)(n0 + n) * INF_ + k0 + grp);
    uint4* dl = (uint4*)(d_wtlo + (size_t)(n0 + n) * INF_ + k0 + grp);
    dh[0] = hi2[0]; dh[1] = hi2[1];
    dl[0] = lo2[0]; dl[1] = lo2[1];
}

// ============================================================
// Kernel A: g = x @ W via HMMA (3-pass split). grid (48, 8), 128 thr.
// Tile 64i x 64n (one full head). Epilogue: d_g + transposed split gT.
// ============================================================
constexpr int BROW = 264;                       // fp16 row stride (256 + 8 pad)
constexpr int GEMM_SMEM = 2 * 64 * BROW * 2;    // 67584 B

__global__ void __launch_bounds__(128, 1) gemm_tc(void) {
    extern __shared__ char gsm[];
    __half* Bhi = (__half*)gsm;                 // [64][264]
    __half* Blo = Bhi + 64 * BROW;
    int t = threadIdx.x, lane = t & 31, w = t >> 5;
    int m0 = blockIdx.x * 64, h = blockIdx.y, n0 = h * FF;

    #pragma unroll
    for (int q = 0; q < 16; q++) {
        int idx = t + q * 128;                  // 2048 per array
        int n = idx >> 5, c = idx & 31;
        cp16(Bhi + n * BROW + c * 8, d_wthi + (size_t)(n0 + n) * INF_ + c * 8);
        cp16(Blo + n * BROW + c * 8, d_wtlo + (size_t)(n0 + n) * INF_ + c * 8);
    }
    CP_COMMIT(); CP_WAIT(0);
    __syncthreads();

    int gid = lane >> 2, tig = lane & 3;
    const uint2* xh0 = (const uint2*)(d_xphi + (size_t)(m0 + w * 16 + gid) * INF_);
    const uint2* xh8 = (const uint2*)(d_xphi + (size_t)(m0 + w * 16 + gid + 8) * INF_);
    const uint2* xl0 = (const uint2*)(d_xplo + (size_t)(m0 + w * 16 + gid) * INF_);
    const uint2* xl8 = (const uint2*)(d_xplo + (size_t)(m0 + w * 16 + gid + 8) * INF_);

    float d[8][4] = {};
    #pragma unroll 4
    for (int s = 0; s < 16; s++) {
        uint2 ah0 = xh0[s * 4 + tig], ah8 = xh8[s * 4 + tig];
        uint2 al0 = xl0[s * 4 + tig], al8 = xl8[s * 4 + tig];
        uint32_t Ahi[4] = {ah0.x, ah8.x, ah0.y, ah8.y};
        uint32_t Alo[4] = {al0.x, al8.x, al0.y, al8.y};
        #pragma unroll
        for (int nt = 0; nt < 8; nt++) {
            int boff = (nt * 8 + gid) * BROW + s * 16 + 4 * tig;
            uint2 bh = *(const uint2*)(Bhi + boff);
            uint2 bl = *(const uint2*)(Blo + boff);
            mma16816(d[nt], Ahi, bh.x, bh.y);
            mma16816(d[nt], Ahi, bl.x, bl.y);
            mma16816(d[nt], Alo, bh.x, bh.y);
        }
    }
    __syncthreads();    // B dead; overlay transpose buffer

    float* trans = (float*)gsm;     // [64][66]
    int r1 = w * 16 + gid, r2 = r1 + 8;
    #pragma unroll
    for (int nt = 0; nt < 8; nt++) {
        int cc = nt * 8 + 2 * tig;
        trans[r1 * 66 + cc] = d[nt][0]; trans[r1 * 66 + cc + 1] = d[nt][1];
        trans[r2 * 66 + cc] = d[nt][2]; trans[r2 * 66 + cc + 1] = d[nt][3];
    }
    __syncthreads();

    // write d_g rows (fp32)
    {
        int r = t >> 1, half = t & 1;
        float* src = trans + r * 66 + 32 * half;
        float* dst = d_g + (size_t)(m0 + r) * OUTF + n0 + 32 * half;
        #pragma unroll
        for (int q = 0; q < 8; q++)
            *(float4*)(dst + q * 4) = make_float4(src[q * 4], src[q * 4 + 1],
                                                  src[q * 4 + 2], src[q * 4 + 3]);
    }
    // write gT split, j-permuted: d_gthi[h][f][j']
    {
        int f = t >> 1, half = t & 1;
        #pragma unroll
        for (int jq = 0; jq < 2; jq++) {
            int p0 = 32 * half + jq * 16;      // 16 consecutive output positions
            uint4 hi2[2], lo2[2];
            split16(trans + p0 * 66 + f, 66, hi2, lo2);  // grp-aligned: KTAB within
            uint4* dh = (uint4*)(d_gthi + ((size_t)h * FF + f) * NN + m0 + p0);
            uint4* dl = (uint4*)(d_gtlo + ((size_t)h * FF + f) * NN + m0 + p0);
            dh[0] = hi2[0]; dh[1] = hi2[1];
            dl[0] = lo2[0]; dl[1] = lo2[1];
        }
    }
}

// ============================================================
// Kernel B: scores s_l, s_r
// ============================================================
__global__ void score_kernel(const float* __restrict__ aw) {
    int i = blockIdx.x;
    int t = threadIdx.x, h = t >> 5, l = t & 31;
    const float* gr = d_g + (size_t)i * OUTF + h * FF;
    float a0 = gr[l], a1 = gr[l + 32];
    float sl = a0 * aw[l]      + a1 * aw[l + 32];
    float sr = a0 * aw[64 + l] + a1 * aw[96 + l];
    #pragma unroll
    for (int o = 16; o; o >>= 1) {
        sl += __shfl_down_sync(0xffffffffu, sl, o);
        sr += __shfl_down_sync(0xffffffffu, sr, o);
    }
    if (l == 0) { d_sl[i * HH + h] = sl; d_sr[i * HH + h] = sr; }
}

// ============================================================
// Kernel C: per-row adj scan -> m[i,h], C; packs adj to bits
// ============================================================
__global__ void rowc_kernel(const int* __restrict__ adj) {
    int i = blockIdx.x, t = threadIdx.x;
    float mx[8];
    #pragma unroll
    for (int h = 0; h < 8; h++) mx[h] = -3.0e38f;
    int any0 = 0;
    const int* ar = adj + (size_t)i * NN;
    for (int j = t; j < NN; j += 256) {
        int a = ar[j];
        uint32_t bal = __ballot_sync(0xffffffffu, a != 0);
        if ((t & 31) == 0) d_adjbits[i * NW + (j >> 5)] = bal;
        if (a) {
            const float4* p = (const float4*)(d_sr + j * HH);
            float4 v0 = p[0], v1 = p[1];
            mx[0] = fmaxf(mx[0], v0.x); mx[1] = fmaxf(mx[1], v0.y);
            mx[2] = fmaxf(mx[2], v0.z); mx[3] = fmaxf(mx[3], v0.w);
            mx[4] = fmaxf(mx[4], v1.x); mx[5] = fmaxf(mx[5], v1.y);
            mx[6] = fmaxf(mx[6], v1.z); mx[7] = fmaxf(mx[7], v1.w);
        } else any0 = 1;
    }
    __shared__ float wmax[8][8];
    __shared__ int s_any;
    if (t == 0) s_any = 0;
    __syncthreads();
    if (any0) s_any = 1;
    int lane = t & 31, wid = t >> 5;
    #pragma unroll
    for (int h = 0; h < 8; h++) {
        float v = mx[h];
        #pragma unroll
        for (int o = 16; o; o >>= 1) v = fmaxf(v, __shfl_down_sync(0xffffffffu, v, o));
        if (lane == 0) wmax[h][wid] = v;
    }
    __syncthreads();
    if (t < 8) {
        int h = t;
        float mradj = wmax[h][0];
        #pragma unroll
        for (int w = 1; w < 8; w++) mradj = fmaxf(mradj, wmax[h][w]);
        float sl = d_sl[i * HH + h];
        float s  = sl + mradj;
        float lk = fmaxf(s, 0.2f * s);
        float m  = s_any ? fmaxf(1.0f, lk) : lk;
        d_m[i * HH + h]  = m;
        d_Cc[i * HH + h] = s_any ? expf(1.0f - m) : 0.0f;
    }
}

// ============================================================
// Kernel F: HMMA main (unchanged from R5). 128 CTAs, 384 thr.
// ============================================================
constexpr int BSM_HALVES = 2 * 4 * 64 * 80;
constexpr int OFF_SR = BSM_HALVES * 2;
constexpr int OFF_Z  = OFF_SR + 2 * 2 * 64 * 4;
constexpr int SMEM_TC = OFF_Z + MI * 2 * 4;

__global__ void __launch_bounds__(384, 1) gat_tc(float* __restrict__ out) {
    extern __shared__ char smem[];
    __half* Bsm = (__half*)smem;
    float* sr_s = (float*)(smem + OFF_SR);
    float* Z_s  = (float*)(smem + OFF_Z);

    int t = threadIdx.x, lane = t & 31, w = t >> 5;
    int hp = blockIdx.x & 3;
    int i0 = (blockIdx.x >> 2) * MI;
    int hl = (w >= 6), mt = (w >= 6) ? w - 6 : w;
    int gid = lane >> 2, tig = lane & 3;
    int r0 = mt * 16 + gid;

    int gi0 = (i0 + r0) * HH + hp * 2 + hl;
    float sl0 = d_sl[gi0], m0v = d_m[gi0], C0 = d_Cc[gi0];
    int gi1 = gi0 + 8 * HH;
    float sl1 = d_sl[gi1], m1v = d_m[gi1], C1 = d_Cc[gi1];

    const uint32_t* ab0 = d_adjbits + (size_t)(i0 + r0) * NW;
    const uint32_t* ab1 = ab0 + 8 * NW;

    float d[8][4] = {};
    float zA = 0.f, zB = 0.f;

    auto stage = [&](int buf, int jt) {
        int j0 = jt * KT;
        #pragma unroll
        for (int k = 0; k < 6; k++) {
            int idx = t + k * 384;
            if (idx < 2048) {
                int reg = idx >> 9;
                int shl = reg >> 1, sp = reg & 1;
                int rc = idx & 511;
                int f = rc >> 3, c = rc & 7;
                const __half* src = (sp ? d_gtlo : d_gthi)
                    + ((size_t)(hp * 2 + shl) * FF + f) * NN + j0 + c * 8;
                cp16(Bsm + (size_t)((buf * 4 + reg) * 64 + f) * 80 + c * 8, src);
            }
        }
        if (t < 128) {
            int head = t >> 6, p = t & 63;
            int j = j0 + (p & ~15) + KTAB(p & 15);
            cp4(&sr_s[(buf * 2 + head) * 64 + p],
                d_sr + (size_t)j * HH + hp * 2 + head);
        }
    };

    stage(0, 0);
    CP_COMMIT();

    for (int jt = 0; jt < NT; ++jt) {
        int buf = jt & 1, nb = buf ^ 1;
        if (jt + 1 < NT) { stage(nb, jt + 1); CP_COMMIT(); CP_WAIT(1); }
        else             { CP_WAIT(0); }
        __syncthreads();

        uint2 bw0 = *(const uint2*)(ab0 + jt * 2);
        uint2 bw1 = *(const uint2*)(ab1 + jt * 2);
        uint64_t bits0 = (uint64_t)bw0.x | ((uint64_t)bw0.y << 32);
        uint64_t bits1 = (uint64_t)bw1.x | ((uint64_t)bw1.y << 32);

        uint32_t A[4][4];
        const float* srh = sr_s + (buf * 2 + hl) * 64;
        #pragma unroll
        for (int s = 0; s < 4; s++) {
            float4 sv = *(const float4*)(srh + s * 16 + 4 * tig);
            int jb = s * 16 + 2 * tig;
            float q0 = sl0 + sv.x, q1 = sl0 + sv.y, q2 = sl0 + sv.z, q3 = sl0 + sv.w;
            float e00 = __expf(fmaxf(q0, 0.2f * q0) - m0v);
            float e01 = __expf(fmaxf(q1, 0.2f * q1) - m0v);
            float e02 = __expf(fmaxf(q2, 0.2f * q2) - m0v);
            float e03 = __expf(fmaxf(q3, 0.2f * q3) - m0v);
            float w00 = ((bits0 >> jb) & 1)       ? e00 : C0;
            float w01 = ((bits0 >> (jb + 1)) & 1) ? e01 : C0;
            float w02 = ((bits0 >> (jb + 8)) & 1) ? e02 : C0;
            float w03 = ((bits0 >> (jb + 9)) & 1) ? e03 : C0;
            float p0 = sl1 + sv.x, p1 = sl1 + sv.y, p2 = sl1 + sv.z, p3 = sl1 + sv.w;
            float e10 = __expf(fmaxf(p0, 0.2f * p0) - m1v);
            float e11 = __expf(fmaxf(p1, 0.2f * p1) - m1v);
            float e12 = __expf(fmaxf(p2, 0.2f * p2) - m1v);
            float e13 = __expf(fmaxf(p3, 0.2f * p3) - m1v);
            float w10 = ((bits1 >> jb) & 1)       ? e10 : C1;
            float w11 = ((bits1 >> (jb + 1)) & 1) ? e11 : C1;
            float w12 = ((bits1 >> (jb + 8)) & 1) ? e12 : C1;
            float w13 = ((bits1 >> (jb + 9)) & 1) ? e13 : C1;
            zA += (w00 + w01) + (w02 + w03);
            zB += (w10 + w11) + (w12 + w13);
            A[s][0] = ph2(w00, w01);
            A[s][1] = ph2(w10, w11);
            A[s][2] = ph2(w02, w03);
            A[s][3] = ph2(w12, w13);
        }

        #pragma unroll
        for (int sp = 0; sp < 2; sp++) {
            const __half* bb = Bsm + (size_t)((buf * 4 + hl * 2 + sp) * 64) * 80;
            #pragma unroll
            for (int s = 0; s < 4; s++) {
                #pragma unroll
                for (int nt = 0; nt < 8; nt++) {
                    uint2 b = *(const uint2*)(bb + (nt * 8 + gid) * 80 + s * 16 + 4 * tig);
                    mma16816(d[nt], A[s], b.x, b.y);
                }
            }
        }
        __syncthreads();
    }

    zA += __shfl_xor_sync(0xffffffffu, zA, 1);
    zA += __shfl_xor_sync(0xffffffffu, zA, 2);
    zB += __shfl_xor_sync(0xffffffffu, zB, 1);
    zB += __shfl_xor_sync(0xffffffffu, zB, 2);
    if (tig == 0) {
        Z_s[r0 * 2 + hl] = zA;
        Z_s[(r0 + 8) * 2 + hl] = zB;
    }
    __syncthreads();

    float inv0 = 1.0f / Z_s[r0 * 2 + hl];
    float inv1 = 1.0f / Z_s[(r0 + 8) * 2 + hl];
    int col0 = (hp * 2 + hl) * FF + 2 * tig;
    float* o0 = out + (size_t)(i0 + r0) * OUTF + col0;
    float* o1 = out + (size_t)(i0 + r0 + 8) * OUTF + col0;
    #pragma unroll
    for (int nt = 0; nt < 8; nt++) {
        *(float2*)(o0 + nt * 8) = make_float2(d[nt][0] * inv0, d[nt][1] * inv0);
        *(float2*)(o1 + nt * 8) = make_float2(d[nt][2] * inv1, d[nt][3] * inv1);
    }
}

// ============================================================
extern "C" void kernel_launch(void* const* d_in, const int* in_sizes, int n_in,
                              void* d_out, int out_size) {
    const float* x   = (const float*)d_in[0];
    const int*   adj = (const int*)d_in[1];
    const float* W   = (const float*)d_in[2];
    const float* aw  = (const float*)d_in[3];
    float* out = (float*)d_out;

    cudaFuncSetAttribute(gemm_tc, cudaFuncAttributeMaxDynamicSharedMemorySize, GEMM_SMEM);
    cudaFuncSetAttribute(gat_tc, cudaFuncAttributeMaxDynamicSharedMemorySize, SMEM_TC);

    xsplit_kernel<<<NN / 16, 256>>>(x);                       // launch 0
    wsplit_kernel<<<dim3(INF_ / 64, OUTF / 64), 256>>>(W);    // launch 1
    gemm_tc<<<dim3(NN / 64, HH), 128, GEMM_SMEM>>>();         // launch 2
    score_kernel<<<NN, 256>>>(aw);                            // launch 3
    rowc_kernel<<<NN, 256>>>(adj);                            // launch 4
    gat_tc<<<(NN / MI) * 4, 384, SMEM_TC>>>(out);             // launch 5 (ncu -s 5)
}

// round 7
// speedup vs baseline: 5.8546x; 1.2905x over previous
#include <cuda_runtime.h>
#include <cuda_fp16.h>
#include <cstdint>

#define NN    3072
#define HH    8
#define FF    64
#define OUTF  512
#define INF_  256
#define KT    64
#define NT    (NN / KT)     // 48
#define MI    96            // i rows per CTA in gat_tc
#define NW    (NN / 32)     // adj bitmask words per row
#define LOG2E 1.4426950408889634f

// ---- scratch (device globals) ----
__device__ float d_sl[NN * HH];           // pre-scaled by log2(e)
__device__ float d_sr[NN * HH];           // pre-scaled
__device__ float d_m[NN * HH];            // scaled row max
__device__ float d_Cc[NN * HH];           // any0 ? exp2(LOG2E - m) : 0
__device__ uint32_t d_adjbits[NN * NW];
__device__ __half d_gthi[HH * FF * NN];   // g^T fp16 (rn), j-permuted: [h][f][j']
__device__ __half d_xphi[NN * INF_];      // x split hi, k-permuted
__device__ __half d_xplo[NN * INF_];
__device__ __half d_wthi[OUTF * INF_];    // W^T split hi, k-permuted: [n][k']
__device__ __half d_wtlo[OUTF * INF_];

// permutation within 16-group: position p holds actual k = KTAB(p)
#define KTAB(pp) (2 * ((pp) >> 2) + (((pp) & 2) ? 8 : 0) + ((pp) & 1))

// ---------------- helpers ----------------
__device__ __forceinline__ uint32_t smem_u32(const void* p) {
    uint32_t a;
    asm("{ .reg .u64 t; cvta.to.shared.u64 t, %1; cvt.u32.u64 %0, t; }" : "=r"(a) : "l"(p));
    return a;
}
__device__ __forceinline__ void cp16(void* dst, const void* src) {
    asm volatile("cp.async.cg.shared.global [%0], [%1], 16;\n" :: "r"(smem_u32(dst)), "l"(src));
}
__device__ __forceinline__ void cp4(void* dst, const void* src) {
    asm volatile("cp.async.ca.shared.global [%0], [%1], 4;\n" :: "r"(smem_u32(dst)), "l"(src));
}
#define CP_COMMIT() asm volatile("cp.async.commit_group;\n")
#define CP_WAIT(n)  asm volatile("cp.async.wait_group %0;\n" :: "n"(n))

__device__ __forceinline__ void mma16816(float* d, const uint32_t* a,
                                         uint32_t b0, uint32_t b1) {
    asm volatile(
        "mma.sync.aligned.m16n8k16.row.col.f32.f16.f16.f32 "
        "{%0,%1,%2,%3}, {%4,%5,%6,%7}, {%8,%9}, {%0,%1,%2,%3};"
        : "+f"(d[0]), "+f"(d[1]), "+f"(d[2]), "+f"(d[3])
        : "r"(a[0]), "r"(a[1]), "r"(a[2]), "r"(a[3]), "r"(b0), "r"(b1));
}
__device__ __forceinline__ uint32_t ph2(float lo, float hi) {
    __half2 h = __floats2half2_rn(lo, hi);
    return *(uint32_t*)&h;
}
__device__ __forceinline__ void split16(const float* v_strided, int stride,
                                        uint4* hi2, uint4* lo2) {
    uint32_t hw[8], lw[8];
    #pragma unroll
    for (int q = 0; q < 8; q++) {
        float v0 = v_strided[KTAB(2 * q) * stride];
        float v1 = v_strided[KTAB(2 * q + 1) * stride];
        __half h0 = __float2half_rn(v0), h1 = __float2half_rn(v1);
        float r0 = v0 - __half2float(h0), r1 = v1 - __half2float(h1);
        __half l0 = __float2half_rn(r0), l1 = __float2half_rn(r1);
        hw[q] = ((uint32_t)__half_as_ushort(h1) << 16) | __half_as_ushort(h0);
        lw[q] = ((uint32_t)__half_as_ushort(l1) << 16) | __half_as_ushort(l0);
    }
    hi2[0] = make_uint4(hw[0], hw[1], hw[2], hw[3]);
    hi2[1] = make_uint4(hw[4], hw[5], hw[6], hw[7]);
    lo2[0] = make_uint4(lw[0], lw[1], lw[2], lw[3]);
    lo2[1] = make_uint4(lw[4], lw[5], lw[6], lw[7]);
}

// ============================================================
// Kernel 0: prep = xsplit (blocks 0..191) + wsplit (blocks 192..223)
// ============================================================
__global__ void prep_kernel(const float* __restrict__ x, const float* __restrict__ W) {
    int t = threadIdx.x;
    if (blockIdx.x < 192) {
        __shared__ float s[16][257];
        int r0 = blockIdx.x * 16;
        #pragma unroll
        for (int q = 0; q < 4; q++) {
            int idx = t + q * 256;
            int r = idx >> 6, c4 = (idx & 63) * 4;
            float4 v = *(const float4*)(x + (size_t)(r0 + r) * INF_ + c4);
            s[r][c4] = v.x; s[r][c4 + 1] = v.y; s[r][c4 + 2] = v.z; s[r][c4 + 3] = v.w;
        }
        __syncthreads();
        int r = t >> 4, grp = (t & 15) * 16;
        uint4 hi2[2], lo2[2];
        split16(&s[r][grp], 1, hi2, lo2);
        uint4* dh = (uint4*)(d_xphi + (size_t)(r0 + r) * INF_ + grp);
        uint4* dl = (uint4*)(d_xplo + (size_t)(r0 + r) * INF_ + grp);
        dh[0] = hi2[0]; dh[1] = hi2[1];
        dl[0] = lo2[0]; dl[1] = lo2[1];
    } else {
        __shared__ float s[64][65];
        int b = blockIdx.x - 192;
        int k0 = (b & 3) * 64, n0 = (b >> 2) * 64;
        #pragma unroll
        for (int q = 0; q < 4; q++) {
            int idx = t + q * 256;
            int k = idx >> 4, n4 = (idx & 15) * 4;
            float4 v = *(const float4*)(W + (size_t)(k0 + k) * OUTF + n0 + n4);
            s[k][n4] = v.x; s[k][n4 + 1] = v.y; s[k][n4 + 2] = v.z; s[k][n4 + 3] = v.w;
        }
        __syncthreads();
        int n = t >> 2, grp = (t & 3) * 16;
        uint4 hi2[2], lo2[2];
        split16(&s[grp][n], 65, hi2, lo2);
        uint4* dh = (uint4*)(d_wthi + (size_t)(n0 + n) * INF_ + k0 + grp);
        uint4* dl = (uint4*)(d_wtlo + (size_t)(n0 + n) * INF_ + k0 + grp);
        dh[0] = hi2[0]; dh[1] = hi2[1];
        dl[0] = lo2[0]; dl[1] = lo2[1];
    }
}

// ============================================================
// Kernel 1: g = x @ W via HMMA (3-pass split), fused epilogue:
//  - scores s_l, s_r (fp32 dot, scaled by log2e)
//  - g^T fp16-rn, j-permuted (B operand for gat_tc)
// grid (48, 8), 128 thr.
// ============================================================
constexpr int BROW = 264;
constexpr int GEMM_SMEM = 2 * 64 * BROW * 2;    // 67584 B

__global__ void __launch_bounds__(128, 1) gemm_tc(const float* __restrict__ aw) {
    extern __shared__ char gsm[];
    __half* Bhi = (__half*)gsm;
    __half* Blo = Bhi + 64 * BROW;
    int t = threadIdx.x, lane = t & 31, w = t >> 5;
    int m0 = blockIdx.x * 64, h = blockIdx.y, n0 = h * FF;

    #pragma unroll
    for (int q = 0; q < 16; q++) {
        int idx = t + q * 128;
        int n = idx >> 5, c = idx & 31;
        cp16(Bhi + n * BROW + c * 8, d_wthi + (size_t)(n0 + n) * INF_ + c * 8);
        cp16(Blo + n * BROW + c * 8, d_wtlo + (size_t)(n0 + n) * INF_ + c * 8);
    }
    CP_COMMIT(); CP_WAIT(0);
    __syncthreads();

    int gid = lane >> 2, tig = lane & 3;
    const uint2* xh0 = (const uint2*)(d_xphi + (size_t)(m0 + w * 16 + gid) * INF_);
    const uint2* xh8 = (const uint2*)(d_xphi + (size_t)(m0 + w * 16 + gid + 8) * INF_);
    const uint2* xl0 = (const uint2*)(d_xplo + (size_t)(m0 + w * 16 + gid) * INF_);
    const uint2* xl8 = (const uint2*)(d_xplo + (size_t)(m0 + w * 16 + gid + 8) * INF_);

    float d[8][4] = {};
    #pragma unroll 4
    for (int s = 0; s < 16; s++) {
        uint2 ah0 = xh0[s * 4 + tig], ah8 = xh8[s * 4 + tig];
        uint2 al0 = xl0[s * 4 + tig], al8 = xl8[s * 4 + tig];
        uint32_t Ahi[4] = {ah0.x, ah8.x, ah0.y, ah8.y};
        uint32_t Alo[4] = {al0.x, al8.x, al0.y, al8.y};
        #pragma unroll
        for (int nt = 0; nt < 8; nt++) {
            int boff = (nt * 8 + gid) * BROW + s * 16 + 4 * tig;
            uint2 bh = *(const uint2*)(Bhi + boff);
            uint2 bl = *(const uint2*)(Blo + boff);
            mma16816(d[nt], Ahi, bh.x, bh.y);
            mma16816(d[nt], Ahi, bl.x, bl.y);
            mma16816(d[nt], Alo, bh.x, bh.y);
        }
    }
    __syncthreads();    // B dead; overlay transpose buffer

    float* trans = (float*)gsm;     // [64][66]
    int r1 = w * 16 + gid, r2 = r1 + 8;
    #pragma unroll
    for (int nt = 0; nt < 8; nt++) {
        int cc = nt * 8 + 2 * tig;
        trans[r1 * 66 + cc] = d[nt][0]; trans[r1 * 66 + cc + 1] = d[nt][1];
        trans[r2 * 66 + cc] = d[nt][2]; trans[r2 * 66 + cc + 1] = d[nt][3];
    }
    __syncthreads();

    // ---- fused scores: s_l, s_r (x log2e) ----
    {
        int r = t >> 1, half = t & 1;
        const float* row = trans + r * 66 + half * 32;
        const float* awl = aw + half * 32;
        const float* awr = aw + 64 + half * 32;
        float sl = 0.f, sr = 0.f;
        #pragma unroll
        for (int q = 0; q < 32; q++) {
            float gv = row[q];
            sl += gv * awl[q];
            sr += gv * awr[q];
        }
        sl += __shfl_xor_sync(0xffffffffu, sl, 1);
        sr += __shfl_xor_sync(0xffffffffu, sr, 1);
        if (!half) {
            d_sl[(m0 + r) * HH + h] = sl * LOG2E;
            d_sr[(m0 + r) * HH + h] = sr * LOG2E;
        }
    }

    // ---- g^T fp16 (hi only), j-permuted ----
    {
        int f = t >> 1, half = t & 1;
        #pragma unroll
        for (int jq = 0; jq < 2; jq++) {
            int p0 = 32 * half + jq * 16;
            uint32_t hw[8];
            #pragma unroll
            for (int q = 0; q < 8; q++) {
                float v0 = trans[(p0 + KTAB(2 * q)) * 66 + f];
                float v1 = trans[(p0 + KTAB(2 * q + 1)) * 66 + f];
                hw[q] = ph2(v0, v1);
            }
            uint4* dh = (uint4*)(d_gthi + ((size_t)h * FF + f) * NN + m0 + p0);
            dh[0] = make_uint4(hw[0], hw[1], hw[2], hw[3]);
            dh[1] = make_uint4(hw[4], hw[5], hw[6], hw[7]);
        }
    }
}

// ============================================================
// Kernel 2: per-row adj scan -> m[i,h] (scaled), C; packs adj bits
// ============================================================
__global__ void rowc_kernel(const int* __restrict__ adj) {
    int i = blockIdx.x, t = threadIdx.x;
    float mx[8];
    #pragma unroll
    for (int h = 0; h < 8; h++) mx[h] = -3.0e38f;
    int any0 = 0;
    const int* ar = adj + (size_t)i * NN;
    for (int j = t; j < NN; j += 256) {
        int a = ar[j];
        uint32_t bal = __ballot_sync(0xffffffffu, a != 0);
        if ((t & 31) == 0) d_adjbits[i * NW + (j >> 5)] = bal;
        if (a) {
            const float4* p = (const float4*)(d_sr + j * HH);
            float4 v0 = p[0], v1 = p[1];
            mx[0] = fmaxf(mx[0], v0.x); mx[1] = fmaxf(mx[1], v0.y);
            mx[2] = fmaxf(mx[2], v0.z); mx[3] = fmaxf(mx[3], v0.w);
            mx[4] = fmaxf(mx[4], v1.x); mx[5] = fmaxf(mx[5], v1.y);
            mx[6] = fmaxf(mx[6], v1.z); mx[7] = fmaxf(mx[7], v1.w);
        } else any0 = 1;
    }
    __shared__ float wmax[8][8];
    __shared__ int s_any;
    if (t == 0) s_any = 0;
    __syncthreads();
    if (any0) s_any = 1;
    int lane = t & 31, wid = t >> 5;
    #pragma unroll
    for (int h = 0; h < 8; h++) {
        float v = mx[h];
        #pragma unroll
        for (int o = 16; o; o >>= 1) v = fmaxf(v, __shfl_down_sync(0xffffffffu, v, o));
        if (lane == 0) wmax[h][wid] = v;
    }
    __syncthreads();
    if (t < 8) {
        int h = t;
        float mradj = wmax[h][0];
        #pragma unroll
        for (int w = 1; w < 8; w++) mradj = fmaxf(mradj, wmax[h][w]);
        float sl = d_sl[i * HH + h];
        float s  = sl + mradj;                    // scaled
        float lk = fmaxf(s, 0.2f * s);            // scaled leaky
        float m  = s_any ? fmaxf(LOG2E, lk) : lk; // fill value 1 -> LOG2E scaled
        d_m[i * HH + h]  = m;
        d_Cc[i * HH + h] = s_any ? exp2f(LOG2E - m) : 0.0f;
    }
}

// ============================================================
// Kernel 3: HMMA main, single g pass. 128 CTAs, 384 thr, smem 42KB.
// ============================================================
constexpr int BSM_BYTES = 2 * 2 * 64 * 80 * 2;      // 40960
constexpr int OFF_SR = BSM_BYTES;                   // [2][2][64] floats
constexpr int OFF_Z  = OFF_SR + 1024;
constexpr int SMEM_TC = OFF_Z + MI * 2 * 4;         // 42752

__global__ void __launch_bounds__(384, 1) gat_tc(float* __restrict__ out) {
    extern __shared__ char smem[];
    __half* Bsm = (__half*)smem;                    // [buf][head][64f][80]
    float* sr_s = (float*)(smem + OFF_SR);
    float* Z_s  = (float*)(smem + OFF_Z);

    int t = threadIdx.x, lane = t & 31, w = t >> 5;
    int hp = blockIdx.x & 3;
    int i0 = (blockIdx.x >> 2) * MI;
    int hl = (w >= 6), mt = (w >= 6) ? w - 6 : w;
    int gid = lane >> 2, tig = lane & 3;
    int r0 = mt * 16 + gid;

    int gi0 = (i0 + r0) * HH + hp * 2 + hl;
    float sl0 = d_sl[gi0], m0v = d_m[gi0], C0 = d_Cc[gi0];
    int gi1 = gi0 + 8 * HH;
    float sl1 = d_sl[gi1], m1v = d_m[gi1], C1 = d_Cc[gi1];

    const uint32_t* ab0 = d_adjbits + (size_t)(i0 + r0) * NW;
    const uint32_t* ab1 = ab0 + 8 * NW;

    float d[8][4] = {};
    float zA = 0.f, zB = 0.f;

    auto stage = [&](int buf, int jt) {
        int j0 = jt * KT;
        #pragma unroll
        for (int k = 0; k < 3; k++) {
            int idx = t + k * 384;
            if (idx < 1024) {
                int head = idx >> 9;
                int rc = idx & 511;
                int f = rc >> 3, c = rc & 7;
                const __half* src = d_gthi
                    + ((size_t)(hp * 2 + head) * FF + f) * NN + j0 + c * 8;
                cp16(Bsm + (size_t)((buf * 2 + head) * 64 + f) * 80 + c * 8, src);
            }
        }
        if (t < 128) {
            int head = t >> 6, p = t & 63;
            int j = j0 + (p & ~15) + KTAB(p & 15);
            cp4(&sr_s[(buf * 2 + head) * 64 + p],
                d_sr + (size_t)j * HH + hp * 2 + head);
        }
    };

    stage(0, 0);
    CP_COMMIT();

    for (int jt = 0; jt < NT; ++jt) {
        int buf = jt & 1, nb = buf ^ 1;
        if (jt + 1 < NT) { stage(nb, jt + 1); CP_COMMIT(); CP_WAIT(1); }
        else             { CP_WAIT(0); }
        __syncthreads();

        uint2 bw0 = *(const uint2*)(ab0 + jt * 2);
        uint2 bw1 = *(const uint2*)(ab1 + jt * 2);
        uint64_t bits0 = (uint64_t)bw0.x | ((uint64_t)bw0.y << 32);
        uint64_t bits1 = (uint64_t)bw1.x | ((uint64_t)bw1.y << 32);

        uint32_t A[4][4];
        const float* srh = sr_s + (buf * 2 + hl) * 64;
        #pragma unroll
        for (int s = 0; s < 4; s++) {
            float4 sv = *(const float4*)(srh + s * 16 + 4 * tig);
            int jb = s * 16 + 2 * tig;
            float q0 = sl0 + sv.x, q1 = sl0 + sv.y, q2 = sl0 + sv.z, q3 = sl0 + sv.w;
            float e00 = exp2f(fmaxf(q0, 0.2f * q0) - m0v);
            float e01 = exp2f(fmaxf(q1, 0.2f * q1) - m0v);
            float e02 = exp2f(fmaxf(q2, 0.2f * q2) - m0v);
            float e03 = exp2f(fmaxf(q3, 0.2f * q3) - m0v);
            float w00 = ((bits0 >> jb) & 1)       ? e00 : C0;
            float w01 = ((bits0 >> (jb + 1)) & 1) ? e01 : C0;
            float w02 = ((bits0 >> (jb + 8)) & 1) ? e02 : C0;
            float w03 = ((bits0 >> (jb + 9)) & 1) ? e03 : C0;
            float p0 = sl1 + sv.x, p1 = sl1 + sv.y, p2 = sl1 + sv.z, p3 = sl1 + sv.w;
            float e10 = exp2f(fmaxf(p0, 0.2f * p0) - m1v);
            float e11 = exp2f(fmaxf(p1, 0.2f * p1) - m1v);
            float e12 = exp2f(fmaxf(p2, 0.2f * p2) - m1v);
            float e13 = exp2f(fmaxf(p3, 0.2f * p3) - m1v);
            float w10 = ((bits1 >> jb) & 1)       ? e10 : C1;
            float w11 = ((bits1 >> (jb + 1)) & 1) ? e11 : C1;
            float w12 = ((bits1 >> (jb + 8)) & 1) ? e12 : C1;
            float w13 = ((bits1 >> (jb + 9)) & 1) ? e13 : C1;
            zA += (w00 + w01) + (w02 + w03);
            zB += (w10 + w11) + (w12 + w13);
            A[s][0] = ph2(w00, w01);
            A[s][1] = ph2(w10, w11);
            A[s][2] = ph2(w02, w03);
            A[s][3] = ph2(w12, w13);
        }

        const __half* bb = Bsm + (size_t)((buf * 2 + hl) * 64) * 80;
        #pragma unroll
        for (int s = 0; s < 4; s++) {
            #pragma unroll
            for (int nt = 0; nt < 8; nt++) {
                uint2 b = *(const uint2*)(bb + (nt * 8 + gid) * 80 + s * 16 + 4 * tig);
                mma16816(d[nt], A[s], b.x, b.y);
            }
        }
        __syncthreads();
    }

    zA += __shfl_xor_sync(0xffffffffu, zA, 1);
    zA += __shfl_xor_sync(0xffffffffu, zA, 2);
    zB += __shfl_xor_sync(0xffffffffu, zB, 1);
    zB += __shfl_xor_sync(0xffffffffu, zB, 2);
    if (tig == 0) {
        Z_s[r0 * 2 + hl] = zA;
        Z_s[(r0 + 8) * 2 + hl] = zB;
    }
    __syncthreads();

    float inv0 = 1.0f / Z_s[r0 * 2 + hl];
    float inv1 = 1.0f / Z_s[(r0 + 8) * 2 + hl];
    int col0 = (hp * 2 + hl) * FF + 2 * tig;
    float* o0 = out + (size_t)(i0 + r0) * OUTF + col0;
    float* o1 = out + (size_t)(i0 + r0 + 8) * OUTF + col0;
    #pragma unroll
    for (int nt = 0; nt < 8; nt++) {
        *(float2*)(o0 + nt * 8) = make_float2(d[nt][0] * inv0, d[nt][1] * inv0);
        *(float2*)(o1 + nt * 8) = make_float2(d[nt][2] * inv1, d[nt][3] * inv1);
    }
}

// ============================================================
extern "C" void kernel_launch(void* const* d_in, const int* in_sizes, int n_in,
                              void* d_out, int out_size) {
    const float* x   = (const float*)d_in[0];
    const int*   adj = (const int*)d_in[1];
    const float* W   = (const float*)d_in[2];
    const float* aw  = (const float*)d_in[3];
    float* out = (float*)d_out;

    cudaFuncSetAttribute(gemm_tc, cudaFuncAttributeMaxDynamicSharedMemorySize, GEMM_SMEM);
    cudaFuncSetAttribute(gat_tc, cudaFuncAttributeMaxDynamicSharedMemorySize, SMEM_TC);

    prep_kernel<<<224, 256>>>(x, W);                          // launch 0
    gemm_tc<<<dim3(NN / 64, HH), 128, GEMM_SMEM>>>(aw);       // launch 1
    rowc_kernel<<<NN, 256>>>(adj);                            // launch 2
    gat_tc<<<(NN / MI) * 4, 384, SMEM_TC>>>(out);             // launch 3 (profiled)
}

// round 8
// speedup vs baseline: 6.3608x; 1.0864x over previous
#include <cuda_runtime.h>
#include <cuda_fp16.h>
#include <cstdint>

#define NN    3072
#define HH    8
#define FF    64
#define OUTF  512
#define INF_  256
#define KT    64
#define NT    (NN / KT)     // 48
#define MI    96            // i rows per CTA in gat_tc
#define NW    (NN / 32)     // adj bitmask words per row
#define LOG2E 1.4426950408889634f

// ---- scratch (device globals) ----
__device__ float d_sl[NN * HH];           // pre-scaled by log2(e)
__device__ float d_sr[NN * HH];           // pre-scaled
__device__ float d_m[NN * HH];            // scaled row max
__device__ float d_Cc[NN * HH];           // any0 ? exp2(LOG2E - m) : 0
__device__ uint32_t d_adjbits[NN * NW];
__device__ __half d_gthi[HH * FF * NN];   // g^T fp16 (rn), j-permuted: [h][f][j']
__device__ __half d_xphi[NN * INF_];      // x split hi, k-permuted
__device__ __half d_xplo[NN * INF_];
__device__ __half d_wthi[OUTF * INF_];    // W^T split hi, k-permuted: [n][k']
__device__ __half d_wtlo[OUTF * INF_];

// permutation within 16-group: position p holds actual k = KTAB(p)
#define KTAB(pp) (2 * ((pp) >> 2) + (((pp) & 2) ? 8 : 0) + ((pp) & 1))

// ---------------- helpers ----------------
__device__ __forceinline__ uint32_t smem_u32(const void* p) {
    uint32_t a;
    asm("{ .reg .u64 t; cvta.to.shared.u64 t, %1; cvt.u32.u64 %0, t; }" : "=r"(a) : "l"(p));
    return a;
}
__device__ __forceinline__ void cp16(void* dst, const void* src) {
    asm volatile("cp.async.cg.shared.global [%0], [%1], 16;\n" :: "r"(smem_u32(dst)), "l"(src));
}
__device__ __forceinline__ void cp4(void* dst, const void* src) {
    asm volatile("cp.async.ca.shared.global [%0], [%1], 4;\n" :: "r"(smem_u32(dst)), "l"(src));
}
#define CP_COMMIT() asm volatile("cp.async.commit_group;\n")
#define CP_WAIT(n)  asm volatile("cp.async.wait_group %0;\n" :: "n"(n))

__device__ __forceinline__ void mma16816(float* d, const uint32_t* a,
                                         uint32_t b0, uint32_t b1) {
    asm volatile(
        "mma.sync.aligned.m16n8k16.row.col.f32.f16.f16.f32 "
        "{%0,%1,%2,%3}, {%4,%5,%6,%7}, {%8,%9}, {%0,%1,%2,%3};"
        : "+f"(d[0]), "+f"(d[1]), "+f"(d[2]), "+f"(d[3])
        : "r"(a[0]), "r"(a[1]), "r"(a[2]), "r"(a[3]), "r"(b0), "r"(b1));
}
__device__ __forceinline__ uint32_t ph2(float lo, float hi) {
    __half2 h = __floats2half2_rn(lo, hi);
    return *(uint32_t*)&h;
}
__device__ __forceinline__ void split16(const float* v_strided, int stride,
                                        uint4* hi2, uint4* lo2) {
    uint32_t hw[8], lw[8];
    #pragma unroll
    for (int q = 0; q < 8; q++) {
        float v0 = v_strided[KTAB(2 * q) * stride];
        float v1 = v_strided[KTAB(2 * q + 1) * stride];
        __half h0 = __float2half_rn(v0), h1 = __float2half_rn(v1);
        float r0 = v0 - __half2float(h0), r1 = v1 - __half2float(h1);
        __half l0 = __float2half_rn(r0), l1 = __float2half_rn(r1);
        hw[q] = ((uint32_t)__half_as_ushort(h1) << 16) | __half_as_ushort(h0);
        lw[q] = ((uint32_t)__half_as_ushort(l1) << 16) | __half_as_ushort(l0);
    }
    hi2[0] = make_uint4(hw[0], hw[1], hw[2], hw[3]);
    hi2[1] = make_uint4(hw[4], hw[5], hw[6], hw[7]);
    lo2[0] = make_uint4(lw[0], lw[1], lw[2], lw[3]);
    lo2[1] = make_uint4(lw[4], lw[5], lw[6], lw[7]);
}

// ============================================================
// Kernel 0: prep = xsplit (blocks 0..191) + wsplit (blocks 192..223)
// ============================================================
__global__ void prep_kernel(const float* __restrict__ x, const float* __restrict__ W) {
    int t = threadIdx.x;
    if (blockIdx.x < 192) {
        __shared__ float s[16][257];
        int r0 = blockIdx.x * 16;
        #pragma unroll
        for (int q = 0; q < 4; q++) {
            int idx = t + q * 256;
            int r = idx >> 6, c4 = (idx & 63) * 4;
            float4 v = *(const float4*)(x + (size_t)(r0 + r) * INF_ + c4);
            s[r][c4] = v.x; s[r][c4 + 1] = v.y; s[r][c4 + 2] = v.z; s[r][c4 + 3] = v.w;
        }
        __syncthreads();
        int r = t >> 4, grp = (t & 15) * 16;
        uint4 hi2[2], lo2[2];
        split16(&s[r][grp], 1, hi2, lo2);
        uint4* dh = (uint4*)(d_xphi + (size_t)(r0 + r) * INF_ + grp);
        uint4* dl = (uint4*)(d_xplo + (size_t)(r0 + r) * INF_ + grp);
        dh[0] = hi2[0]; dh[1] = hi2[1];
        dl[0] = lo2[0]; dl[1] = lo2[1];
    } else {
        __shared__ float s[64][65];
        int b = blockIdx.x - 192;
        int k0 = (b & 3) * 64, n0 = (b >> 2) * 64;
        #pragma unroll
        for (int q = 0; q < 4; q++) {
            int idx = t + q * 256;
            int k = idx >> 4, n4 = (idx & 15) * 4;
            float4 v = *(const float4*)(W + (size_t)(k0 + k) * OUTF + n0 + n4);
            s[k][n4] = v.x; s[k][n4 + 1] = v.y; s[k][n4 + 2] = v.z; s[k][n4 + 3] = v.w;
        }
        __syncthreads();
        int n = t >> 2, grp = (t & 3) * 16;
        uint4 hi2[2], lo2[2];
        split16(&s[grp][n], 65, hi2, lo2);
        uint4* dh = (uint4*)(d_wthi + (size_t)(n0 + n) * INF_ + k0 + grp);
        uint4* dl = (uint4*)(d_wtlo + (size_t)(n0 + n) * INF_ + k0 + grp);
        dh[0] = hi2[0]; dh[1] = hi2[1];
        dl[0] = lo2[0]; dl[1] = lo2[1];
    }
}

// ============================================================
// Kernel 1: g = x @ W via HMMA (3-pass split), fused epilogue:
// scores (scaled) + g^T fp16 j-permuted. grid (48, 8), 128 thr.
// ============================================================
constexpr int BROW = 264;
constexpr int GEMM_SMEM = 2 * 64 * BROW * 2;    // 67584 B

__global__ void __launch_bounds__(128, 1) gemm_tc(const float* __restrict__ aw) {
    extern __shared__ char gsm[];
    __half* Bhi = (__half*)gsm;
    __half* Blo = Bhi + 64 * BROW;
    int t = threadIdx.x, lane = t & 31, w = t >> 5;
    int m0 = blockIdx.x * 64, h = blockIdx.y, n0 = h * FF;

    #pragma unroll
    for (int q = 0; q < 16; q++) {
        int idx = t + q * 128;
        int n = idx >> 5, c = idx & 31;
        cp16(Bhi + n * BROW + c * 8, d_wthi + (size_t)(n0 + n) * INF_ + c * 8);
        cp16(Blo + n * BROW + c * 8, d_wtlo + (size_t)(n0 + n) * INF_ + c * 8);
    }
    CP_COMMIT(); CP_WAIT(0);
    __syncthreads();

    int gid = lane >> 2, tig = lane & 3;
    const uint2* xh0 = (const uint2*)(d_xphi + (size_t)(m0 + w * 16 + gid) * INF_);
    const uint2* xh8 = (const uint2*)(d_xphi + (size_t)(m0 + w * 16 + gid + 8) * INF_);
    const uint2* xl0 = (const uint2*)(d_xplo + (size_t)(m0 + w * 16 + gid) * INF_);
    const uint2* xl8 = (const uint2*)(d_xplo + (size_t)(m0 + w * 16 + gid + 8) * INF_);

    float d[8][4] = {};
    #pragma unroll 4
    for (int s = 0; s < 16; s++) {
        uint2 ah0 = xh0[s * 4 + tig], ah8 = xh8[s * 4 + tig];
        uint2 al0 = xl0[s * 4 + tig], al8 = xl8[s * 4 + tig];
        uint32_t Ahi[4] = {ah0.x, ah8.x, ah0.y, ah8.y};
        uint32_t Alo[4] = {al0.x, al8.x, al0.y, al8.y};
        #pragma unroll
        for (int nt = 0; nt < 8; nt++) {
            int boff = (nt * 8 + gid) * BROW + s * 16 + 4 * tig;
            uint2 bh = *(const uint2*)(Bhi + boff);
            uint2 bl = *(const uint2*)(Blo + boff);
            mma16816(d[nt], Ahi, bh.x, bh.y);
            mma16816(d[nt], Ahi, bl.x, bl.y);
            mma16816(d[nt], Alo, bh.x, bh.y);
        }
    }
    __syncthreads();    // B dead; overlay transpose buffer

    float* trans = (float*)gsm;     // [64][66]
    int r1 = w * 16 + gid, r2 = r1 + 8;
    #pragma unroll
    for (int nt = 0; nt < 8; nt++) {
        int cc = nt * 8 + 2 * tig;
        trans[r1 * 66 + cc] = d[nt][0]; trans[r1 * 66 + cc + 1] = d[nt][1];
        trans[r2 * 66 + cc] = d[nt][2]; trans[r2 * 66 + cc + 1] = d[nt][3];
    }
    __syncthreads();

    // ---- fused scores (x log2e) ----
    {
        int r = t >> 1, half = t & 1;
        const float* row = trans + r * 66 + half * 32;
        const float* awl = aw + half * 32;
        const float* awr = aw + 64 + half * 32;
        float sl = 0.f, sr = 0.f;
        #pragma unroll
        for (int q = 0; q < 32; q++) {
            float gv = row[q];
            sl += gv * awl[q];
            sr += gv * awr[q];
        }
        sl += __shfl_xor_sync(0xffffffffu, sl, 1);
        sr += __shfl_xor_sync(0xffffffffu, sr, 1);
        if (!half) {
            d_sl[(m0 + r) * HH + h] = sl * LOG2E;
            d_sr[(m0 + r) * HH + h] = sr * LOG2E;
        }
    }

    // ---- g^T fp16 (hi only), j-permuted ----
    {
        int f = t >> 1, half = t & 1;
        #pragma unroll
        for (int jq = 0; jq < 2; jq++) {
            int p0 = 32 * half + jq * 16;
            uint32_t hw[8];
            #pragma unroll
            for (int q = 0; q < 8; q++) {
                float v0 = trans[(p0 + KTAB(2 * q)) * 66 + f];
                float v1 = trans[(p0 + KTAB(2 * q + 1)) * 66 + f];
                hw[q] = ph2(v0, v1);
            }
            uint4* dh = (uint4*)(d_gthi + ((size_t)h * FF + f) * NN + m0 + p0);
            dh[0] = make_uint4(hw[0], hw[1], hw[2], hw[3]);
            dh[1] = make_uint4(hw[4], hw[5], hw[6], hw[7]);
        }
    }
}

// ============================================================
// Kernel 2: per-row adj scan -> m[i,h] (scaled), C; packs adj bits
// ============================================================
__global__ void rowc_kernel(const int* __restrict__ adj) {
    int i = blockIdx.x, t = threadIdx.x;
    float mx[8];
    #pragma unroll
    for (int h = 0; h < 8; h++) mx[h] = -3.0e38f;
    int any0 = 0;
    const int* ar = adj + (size_t)i * NN;
    for (int j = t; j < NN; j += 256) {
        int a = ar[j];
        uint32_t bal = __ballot_sync(0xffffffffu, a != 0);
        if ((t & 31) == 0) d_adjbits[i * NW + (j >> 5)] = bal;
        if (a) {
            const float4* p = (const float4*)(d_sr + j * HH);
            float4 v0 = p[0], v1 = p[1];
            mx[0] = fmaxf(mx[0], v0.x); mx[1] = fmaxf(mx[1], v0.y);
            mx[2] = fmaxf(mx[2], v0.z); mx[3] = fmaxf(mx[3], v0.w);
            mx[4] = fmaxf(mx[4], v1.x); mx[5] = fmaxf(mx[5], v1.y);
            mx[6] = fmaxf(mx[6], v1.z); mx[7] = fmaxf(mx[7], v1.w);
        } else any0 = 1;
    }
    __shared__ float wmax[8][8];
    __shared__ int s_any;
    if (t == 0) s_any = 0;
    __syncthreads();
    if (any0) s_any = 1;
    int lane = t & 31, wid = t >> 5;
    #pragma unroll
    for (int h = 0; h < 8; h++) {
        float v = mx[h];
        #pragma unroll
        for (int o = 16; o; o >>= 1) v = fmaxf(v, __shfl_down_sync(0xffffffffu, v, o));
        if (lane == 0) wmax[h][wid] = v;
    }
    __syncthreads();
    if (t < 8) {
        int h = t;
        float mradj = wmax[h][0];
        #pragma unroll
        for (int w = 1; w < 8; w++) mradj = fmaxf(mradj, wmax[h][w]);
        float sl = d_sl[i * HH + h];
        float s  = sl + mradj;
        float lk = fmaxf(s, 0.2f * s);
        float m  = s_any ? fmaxf(LOG2E, lk) : lk;
        d_m[i * HH + h]  = m;
        d_Cc[i * HH + h] = s_any ? exp2f(LOG2E - m) : 0.0f;
    }
}

// ============================================================
// Kernel 3: HMMA main. 3-stage pipeline, 1 sync/tile, hoisted staging,
// z via ones-column MMA. 128 CTAs, 384 thr.
// ============================================================
constexpr int BUF_BYTES = 2 * 64 * 80 * 2;          // 20480 per stage
constexpr int OFF_SR3   = 3 * BUF_BYTES;            // 61440
constexpr int SMEM_TC   = OFF_SR3 + 3 * 512;        // 62976

__global__ void __launch_bounds__(384, 1) gat_tc(float* __restrict__ out) {
    extern __shared__ char smem[];

    int t = threadIdx.x, lane = t & 31, w = t >> 5;
    int hp = blockIdx.x & 3;
    int i0 = (blockIdx.x >> 2) * MI;
    int hl = (w >= 6), mt = (w >= 6) ? w - 6 : w;
    int gid = lane >> 2, tig = lane & 3;
    int t2 = 2 * tig;
    int r0 = mt * 16 + gid;

    // per-row constants (rows r0 and r0+8, head hp*2+hl)
    int gi0 = (i0 + r0) * HH + hp * 2 + hl;
    int gi1 = gi0 + 8 * HH;
    float mA = d_m[gi0], mB = d_m[gi1];
    float slmA = d_sl[gi0] - mA, slmB = d_sl[gi1] - mB;
    float cmA = -0.8f * mA, cmB = -0.8f * mB;
    float CA = d_Cc[gi0], CB = d_Cc[gi1];

    const uint32_t* ab0 = d_adjbits + (size_t)(i0 + r0) * NW;
    const uint32_t* ab1 = ab0 + 8 * NW;

    // ---- hoisted staging descriptors ----
    const char* g_src[3];
    uint32_t g_dst[3];
    int nit = (t < 256) ? 3 : 2;
    #pragma unroll
    for (int q = 0; q < 3; q++) {
        int idx = t + q * 384;
        if (idx < 1024) {
            int head = idx >> 9, rc = idx & 511;
            int f = rc >> 3, c = rc & 7;
            g_src[q] = (const char*)(d_gthi + ((size_t)(hp * 2 + head) * FF + f) * NN + c * 8);
            g_dst[q] = (uint32_t)(((head * 64 + f) * 80 + c * 8) * 2);
        }
    }
    const char* s_src = nullptr;
    uint32_t s_dst = 0;
    if (t < 128) {
        int head = t >> 6, p = t & 63;
        int joff = (p & ~15) + KTAB(p & 15);
        s_src = (const char*)(d_sr + (size_t)joff * HH + hp * 2 + head);
        s_dst = (uint32_t)((head * 64 + p) * 4);
    }

    auto stage = [&](int bi) {
        uint32_t boff = bi * BUF_BYTES;
        #pragma unroll
        for (int q = 0; q < 3; q++) {
            if (q < nit) {
                cp16(smem + boff + g_dst[q], g_src[q]);
                g_src[q] += 64 * 2;       // +64 j (halfs)
            }
        }
        if (t < 128) {
            cp4(smem + OFF_SR3 + bi * 512 + s_dst, s_src);
            s_src += 64 * HH * 4;         // +64 j (floats, stride HH)
        }
    };

    float d[8][4] = {};
    float dz[4] = {};
    uint32_t bz = (gid == 0) ? 0x3C003C00u : 0u;   // ones column (n=0)

    stage(0); CP_COMMIT();
    stage(1); CP_COMMIT();
    int cur = 0, stg = 2;

    for (int jt = 0; jt < NT; ++jt) {
        if (jt < NT - 1) CP_WAIT(1); else CP_WAIT(0);
        __syncthreads();
        if (jt + 2 < NT) { stage(stg); CP_COMMIT(); stg = (stg == 2) ? 0 : stg + 1; }

        uint2 bw0 = *(const uint2*)(ab0 + jt * 2);
        uint2 bw1 = *(const uint2*)(ab1 + jt * 2);
        const float* srh = (const float*)(smem + OFF_SR3 + cur * 512) + hl * 64;

        uint32_t A[4][4];
        #pragma unroll
        for (int s = 0; s < 4; s++) {
            float4 sv = *(const float4*)(srh + s * 16 + 4 * tig);
            uint32_t shA = ((s < 2) ? bw0.x : bw0.y) >> (((s & 1) << 4) + t2);
            uint32_t shB = ((s < 2) ? bw1.x : bw1.y) >> (((s & 1) << 4) + t2);
            // row r0
            float u0 = sv.x + slmA, u1 = sv.y + slmA, u2 = sv.z + slmA, u3 = sv.w + slmA;
            float e0 = exp2f(fmaxf(u0, fmaf(u0, 0.2f, cmA)));
            float e1 = exp2f(fmaxf(u1, fmaf(u1, 0.2f, cmA)));
            float e2 = exp2f(fmaxf(u2, fmaf(u2, 0.2f, cmA)));
            float e3 = exp2f(fmaxf(u3, fmaf(u3, 0.2f, cmA)));
            float w00 = (shA & 1u)   ? e0 : CA;
            float w01 = (shA & 2u)   ? e1 : CA;
            float w02 = (shA & 256u) ? e2 : CA;
            float w03 = (shA & 512u) ? e3 : CA;
            // row r0+8
            float v0 = sv.x + slmB, v1 = sv.y + slmB, v2 = sv.z + slmB, v3 = sv.w + slmB;
            float f0 = exp2f(fmaxf(v0, fmaf(v0, 0.2f, cmB)));
            float f1 = exp2f(fmaxf(v1, fmaf(v1, 0.2f, cmB)));
            float f2 = exp2f(fmaxf(v2, fmaf(v2, 0.2f, cmB)));
            float f3 = exp2f(fmaxf(v3, fmaf(v3, 0.2f, cmB)));
            float w10 = (shB & 1u)   ? f0 : CB;
            float w11 = (shB & 2u)   ? f1 : CB;
            float w12 = (shB & 256u) ? f2 : CB;
            float w13 = (shB & 512u) ? f3 : CB;
            A[s][0] = ph2(w00, w01);
            A[s][1] = ph2(w10, w11);
            A[s][2] = ph2(w02, w03);
            A[s][3] = ph2(w12, w13);
            mma16816(dz, A[s], bz, bz);     // z accumulation on tensor pipe
        }

        const __half* bb = (const __half*)(smem + cur * BUF_BYTES) + hl * 64 * 80;
        #pragma unroll
        for (int s = 0; s < 4; s++) {
            #pragma unroll
            for (int nt = 0; nt < 8; nt++) {
                uint2 b = *(const uint2*)(bb + (nt * 8 + gid) * 80 + s * 16 + 4 * tig);
                mma16816(d[nt], A[s], b.x, b.y);
            }
        }
        cur = (cur == 2) ? 0 : cur + 1;
    }

    // ---- epilogue: z lives in dz[0]/dz[2] of tig==0 lanes ----
    float zA = __shfl_sync(0xffffffffu, dz[0], lane & ~3);
    float zB = __shfl_sync(0xffffffffu, dz[2], lane & ~3);
    float inv0 = 1.0f / zA;
    float inv1 = 1.0f / zB;
    int col0 = (hp * 2 + hl) * FF + 2 * tig;
    float* o0 = out + (size_t)(i0 + r0) * OUTF + col0;
    float* o1 = out + (size_t)(i0 + r0 + 8) * OUTF + col0;
    #pragma unroll
    for (int nt = 0; nt < 8; nt++) {
        *(float2*)(o0 + nt * 8) = make_float2(d[nt][0] * inv0, d[nt][1] * inv0);
        *(float2*)(o1 + nt * 8) = make_float2(d[nt][2] * inv1, d[nt][3] * inv1);
    }
}

// ============================================================
extern "C" void kernel_launch(void* const* d_in, const int* in_sizes, int n_in,
                              void* d_out, int out_size) {
    const float* x   = (const float*)d_in[0];
    const int*   adj = (const int*)d_in[1];
    const float* W   = (const float*)d_in[2];
    const float* aw  = (const float*)d_in[3];
    float* out = (float*)d_out;

    cudaFuncSetAttribute(gemm_tc, cudaFuncAttributeMaxDynamicSharedMemorySize, GEMM_SMEM);
    cudaFuncSetAttribute(gat_tc, cudaFuncAttributeMaxDynamicSharedMemorySize, SMEM_TC);

    prep_kernel<<<224, 256>>>(x, W);                          // launch 0
    gemm_tc<<<dim3(NN / 64, HH), 128, GEMM_SMEM>>>(aw);       // launch 1
    rowc_kernel<<<NN, 256>>>(adj);                            // launch 2
    gat_tc<<<(NN / MI) * 4, 384, SMEM_TC>>>(out);             // launch 3 (profiled)
}

// round 9
// speedup vs baseline: 6.5812x; 1.0347x over previous
#include <cuda_runtime.h>
#include <cuda_fp16.h>
#include <cstdint>

#define NN    3072
#define HH    8
#define FF    64
#define OUTF  512
#define INF_  256
#define KT    64
#define NT    (NN / KT)     // 48
#define MI    96            // i rows per CTA in gat_tc
#define NW    (NN / 32)     // adj bitmask words per row
#define LOG2E 1.4426950408889634f

// ---- scratch (device globals) ----
__device__ float d_sl[NN * HH];           // pre-scaled by log2(e)
__device__ float d_sr[NN * HH];           // pre-scaled
__device__ float d_m[NN * HH];            // scaled row max
__device__ float d_Cc[NN * HH];           // any0 ? exp2(LOG2E - m) : 0
__device__ uint32_t d_adjbits[NN * NW];
__device__ __half d_gthi[HH * FF * NN];   // g^T fp16 (rn), j-permuted: [h][f][j']
__device__ __half d_xphi[NN * INF_];      // x split hi, k-permuted
__device__ __half d_xplo[NN * INF_];
__device__ __half d_wthi[OUTF * INF_];    // W^T split hi, k-permuted: [n][k']
__device__ __half d_wtlo[OUTF * INF_];

// permutation within 16-group: position p holds actual k = KTAB(p)
#define KTAB(pp) (2 * ((pp) >> 2) + (((pp) & 2) ? 8 : 0) + ((pp) & 1))

// select LUT: entry (2 mask bits) -> byte_perm selector (e bytes 0-3, C bytes 4-7)
// b01=0 -> 0x7654 (both C), 1 -> 0x7610, 2 -> 0x3254, 3 -> 0x3210 (both e)
static constexpr uint64_t SELLUT = 0x3210325476107654ull;

// ---------------- helpers ----------------
__device__ __forceinline__ uint32_t smem_u32(const void* p) {
    uint32_t a;
    asm("{ .reg .u64 t; cvta.to.shared.u64 t, %1; cvt.u32.u64 %0, t; }" : "=r"(a) : "l"(p));
    return a;
}
__device__ __forceinline__ void cp16(void* dst, const void* src) {
    asm volatile("cp.async.cg.shared.global [%0], [%1], 16;\n" :: "r"(smem_u32(dst)), "l"(src));
}
__device__ __forceinline__ void cp4(void* dst, const void* src) {
    asm volatile("cp.async.ca.shared.global [%0], [%1], 4;\n" :: "r"(smem_u32(dst)), "l"(src));
}
#define CP_COMMIT() asm volatile("cp.async.commit_group;\n")
#define CP_WAIT(n)  asm volatile("cp.async.wait_group %0;\n" :: "n"(n))

__device__ __forceinline__ void mma16816(float* d, const uint32_t* a,
                                         uint32_t b0, uint32_t b1) {
    asm volatile(
        "mma.sync.aligned.m16n8k16.row.col.f32.f16.f16.f32 "
        "{%0,%1,%2,%3}, {%4,%5,%6,%7}, {%8,%9}, {%0,%1,%2,%3};"
        : "+f"(d[0]), "+f"(d[1]), "+f"(d[2]), "+f"(d[3])
        : "r"(a[0]), "r"(a[1]), "r"(a[2]), "r"(a[3]), "r"(b0), "r"(b1));
}
__device__ __forceinline__ uint32_t ph2(float lo, float hi) {
    __half2 h = __floats2half2_rn(lo, hi);
    return *(uint32_t*)&h;
}
__device__ __forceinline__ uint32_t ex2h2(uint32_t a) {
    uint32_t r;
    asm("ex2.approx.f16x2 %0, %1;" : "=r"(r) : "r"(a));
    return r;
}
__device__ __forceinline__ void split16(const float* v_strided, int stride,
                                        uint4* hi2, uint4* lo2) {
    uint32_t hw[8], lw[8];
    #pragma unroll
    for (int q = 0; q < 8; q++) {
        float v0 = v_strided[KTAB(2 * q) * stride];
        float v1 = v_strided[KTAB(2 * q + 1) * stride];
        __half h0 = __float2half_rn(v0), h1 = __float2half_rn(v1);
        float r0 = v0 - __half2float(h0), r1 = v1 - __half2float(h1);
        __half l0 = __float2half_rn(r0), l1 = __float2half_rn(r1);
        hw[q] = ((uint32_t)__half_as_ushort(h1) << 16) | __half_as_ushort(h0);
        lw[q] = ((uint32_t)__half_as_ushort(l1) << 16) | __half_as_ushort(l0);
    }
    hi2[0] = make_uint4(hw[0], hw[1], hw[2], hw[3]);
    hi2[1] = make_uint4(hw[4], hw[5], hw[6], hw[7]);
    lo2[0] = make_uint4(lw[0], lw[1], lw[2], lw[3]);
    lo2[1] = make_uint4(lw[4], lw[5], lw[6], lw[7]);
}

// ============================================================
// Kernel 0: prep = xsplit (blocks 0..191) + wsplit (blocks 192..223)
// ============================================================
__global__ void prep_kernel(const float* __restrict__ x, const float* __restrict__ W) {
    int t = threadIdx.x;
    if (blockIdx.x < 192) {
        __shared__ float s[16][257];
        int r0 = blockIdx.x * 16;
        #pragma unroll
        for (int q = 0; q < 4; q++) {
            int idx = t + q * 256;
            int r = idx >> 6, c4 = (idx & 63) * 4;
            float4 v = *(const float4*)(x + (size_t)(r0 + r) * INF_ + c4);
            s[r][c4] = v.x; s[r][c4 + 1] = v.y; s[r][c4 + 2] = v.z; s[r][c4 + 3] = v.w;
        }
        __syncthreads();
        int r = t >> 4, grp = (t & 15) * 16;
        uint4 hi2[2], lo2[2];
        split16(&s[r][grp], 1, hi2, lo2);
        uint4* dh = (uint4*)(d_xphi + (size_t)(r0 + r) * INF_ + grp);
        uint4* dl = (uint4*)(d_xplo + (size_t)(r0 + r) * INF_ + grp);
        dh[0] = hi2[0]; dh[1] = hi2[1];
        dl[0] = lo2[0]; dl[1] = lo2[1];
    } else {
        __shared__ float s[64][65];
        int b = blockIdx.x - 192;
        int k0 = (b & 3) * 64, n0 = (b >> 2) * 64;
        #pragma unroll
        for (int q = 0; q < 4; q++) {
            int idx = t + q * 256;
            int k = idx >> 4, n4 = (idx & 15) * 4;
            float4 v = *(const float4*)(W + (size_t)(k0 + k) * OUTF + n0 + n4);
            s[k][n4] = v.x; s[k][n4 + 1] = v.y; s[k][n4 + 2] = v.z; s[k][n4 + 3] = v.w;
        }
        __syncthreads();
        int n = t >> 2, grp = (t & 3) * 16;
        uint4 hi2[2], lo2[2];
        split16(&s[grp][n], 65, hi2, lo2);
        uint4* dh = (uint4*)(d_wthi + (size_t)(n0 + n) * INF_ + k0 + grp);
        uint4* dl = (uint4*)(d_wtlo + (size_t)(n0 + n) * INF_ + k0 + grp);
        dh[0] = hi2[0]; dh[1] = hi2[1];
        dl[0] = lo2[0]; dl[1] = lo2[1];
    }
}

// ============================================================
// Kernel 1: g = x @ W via HMMA (3-pass split), fused epilogue:
// scores (scaled) + g^T fp16 j-permuted. grid (48, 8), 128 thr.
// ============================================================
constexpr int BROW = 264;
constexpr int GEMM_SMEM = 2 * 64 * BROW * 2;    // 67584 B

__global__ void __launch_bounds__(128, 1) gemm_tc(const float* __restrict__ aw) {
    extern __shared__ char gsm[];
    __half* Bhi = (__half*)gsm;
    __half* Blo = Bhi + 64 * BROW;
    int t = threadIdx.x, lane = t & 31, w = t >> 5;
    int m0 = blockIdx.x * 64, h = blockIdx.y, n0 = h * FF;

    #pragma unroll
    for (int q = 0; q < 16; q++) {
        int idx = t + q * 128;
        int n = idx >> 5, c = idx & 31;
        cp16(Bhi + n * BROW + c * 8, d_wthi + (size_t)(n0 + n) * INF_ + c * 8);
        cp16(Blo + n * BROW + c * 8, d_wtlo + (size_t)(n0 + n) * INF_ + c * 8);
    }
    CP_COMMIT(); CP_WAIT(0);
    __syncthreads();

    int gid = lane >> 2, tig = lane & 3;
    const uint2* xh0 = (const uint2*)(d_xphi + (size_t)(m0 + w * 16 + gid) * INF_);
    const uint2* xh8 = (const uint2*)(d_xphi + (size_t)(m0 + w * 16 + gid + 8) * INF_);
    const uint2* xl0 = (const uint2*)(d_xplo + (size_t)(m0 + w * 16 + gid) * INF_);
    const uint2* xl8 = (const uint2*)(d_xplo + (size_t)(m0 + w * 16 + gid + 8) * INF_);

    float d[8][4] = {};
    #pragma unroll 4
    for (int s = 0; s < 16; s++) {
        uint2 ah0 = xh0[s * 4 + tig], ah8 = xh8[s * 4 + tig];
        uint2 al0 = xl0[s * 4 + tig], al8 = xl8[s * 4 + tig];
        uint32_t Ahi[4] = {ah0.x, ah8.x, ah0.y, ah8.y};
        uint32_t Alo[4] = {al0.x, al8.x, al0.y, al8.y};
        #pragma unroll
        for (int nt = 0; nt < 8; nt++) {
            int boff = (nt * 8 + gid) * BROW + s * 16 + 4 * tig;
            uint2 bh = *(const uint2*)(Bhi + boff);
            uint2 bl = *(const uint2*)(Blo + boff);
            mma16816(d[nt], Ahi, bh.x, bh.y);
            mma16816(d[nt], Ahi, bl.x, bl.y);
            mma16816(d[nt], Alo, bh.x, bh.y);
        }
    }
    __syncthreads();    // B dead; overlay transpose buffer

    float* trans = (float*)gsm;     // [64][66]
    int r1 = w * 16 + gid, r2 = r1 + 8;
    #pragma unroll
    for (int nt = 0; nt < 8; nt++) {
        int cc = nt * 8 + 2 * tig;
        trans[r1 * 66 + cc] = d[nt][0]; trans[r1 * 66 + cc + 1] = d[nt][1];
        trans[r2 * 66 + cc] = d[nt][2]; trans[r2 * 66 + cc + 1] = d[nt][3];
    }
    __syncthreads();

    // ---- fused scores (x log2e) ----
    {
        int r = t >> 1, half = t & 1;
        const float* row = trans + r * 66 + half * 32;
        const float* awl = aw + half * 32;
        const float* awr = aw + 64 + half * 32;
        float sl = 0.f, sr = 0.f;
        #pragma unroll
        for (int q = 0; q < 32; q++) {
            float gv = row[q];
            sl += gv * awl[q];
            sr += gv * awr[q];
        }
        sl += __shfl_xor_sync(0xffffffffu, sl, 1);
        sr += __shfl_xor_sync(0xffffffffu, sr, 1);
        if (!half) {
            d_sl[(m0 + r) * HH + h] = sl * LOG2E;
            d_sr[(m0 + r) * HH + h] = sr * LOG2E;
        }
    }

    // ---- g^T fp16 (hi only), j-permuted ----
    {
        int f = t >> 1, half = t & 1;
        #pragma unroll
        for (int jq = 0; jq < 2; jq++) {
            int p0 = 32 * half + jq * 16;
            uint32_t hw[8];
            #pragma unroll
            for (int q = 0; q < 8; q++) {
                float v0 = trans[(p0 + KTAB(2 * q)) * 66 + f];
                float v1 = trans[(p0 + KTAB(2 * q + 1)) * 66 + f];
                hw[q] = ph2(v0, v1);
            }
            uint4* dh = (uint4*)(d_gthi + ((size_t)h * FF + f) * NN + m0 + p0);
            dh[0] = make_uint4(hw[0], hw[1], hw[2], hw[3]);
            dh[1] = make_uint4(hw[4], hw[5], hw[6], hw[7]);
        }
    }
}

// ============================================================
// Kernel 2: per-row adj scan -> m[i,h] (scaled), C; packs adj bits
// ============================================================
__global__ void rowc_kernel(const int* __restrict__ adj) {
    int i = blockIdx.x, t = threadIdx.x;
    float mx[8];
    #pragma unroll
    for (int h = 0; h < 8; h++) mx[h] = -3.0e38f;
    int any0 = 0;
    const int* ar = adj + (size_t)i * NN;
    for (int j = t; j < NN; j += 256) {
        int a = ar[j];
        uint32_t bal = __ballot_sync(0xffffffffu, a != 0);
        if ((t & 31) == 0) d_adjbits[i * NW + (j >> 5)] = bal;
        if (a) {
            const float4* p = (const float4*)(d_sr + j * HH);
            float4 v0 = p[0], v1 = p[1];
            mx[0] = fmaxf(mx[0], v0.x); mx[1] = fmaxf(mx[1], v0.y);
            mx[2] = fmaxf(mx[2], v0.z); mx[3] = fmaxf(mx[3], v0.w);
            mx[4] = fmaxf(mx[4], v1.x); mx[5] = fmaxf(mx[5], v1.y);
            mx[6] = fmaxf(mx[6], v1.z); mx[7] = fmaxf(mx[7], v1.w);
        } else any0 = 1;
    }
    __shared__ float wmax[8][8];
    __shared__ int s_any;
    if (t == 0) s_any = 0;
    __syncthreads();
    if (any0) s_any = 1;
    int lane = t & 31, wid = t >> 5;
    #pragma unroll
    for (int h = 0; h < 8; h++) {
        float v = mx[h];
        #pragma unroll
        for (int o = 16; o; o >>= 1) v = fmaxf(v, __shfl_down_sync(0xffffffffu, v, o));
        if (lane == 0) wmax[h][wid] = v;
    }
    __syncthreads();
    if (t < 8) {
        int h = t;
        float mradj = wmax[h][0];
        #pragma unroll
        for (int w = 1; w < 8; w++) mradj = fmaxf(mradj, wmax[h][w]);
        float sl = d_sl[i * HH + h];
        float s  = sl + mradj;
        float lk = fmaxf(s, 0.2f * s);
        float m  = s_any ? fmaxf(LOG2E, lk) : lk;
        d_m[i * HH + h]  = m;
        d_Cc[i * HH + h] = s_any ? exp2f(LOG2E - m) : 0.0f;
    }
}

// ============================================================
// Kernel 3: HMMA main. f16x2 ex2 + PRMT-LUT select w-gen.
// 3-stage pipeline, z via ones-column MMA. 128 CTAs, 384 thr.
// ============================================================
constexpr int BUF_BYTES = 2 * 64 * 80 * 2;          // 20480 per stage
constexpr int OFF_SR3   = 3 * BUF_BYTES;            // 61440
constexpr int SMEM_TC   = OFF_SR3 + 3 * 512;        // 62976

__global__ void __launch_bounds__(384, 1) gat_tc(float* __restrict__ out) {
    extern __shared__ char smem[];

    int t = threadIdx.x, lane = t & 31, w = t >> 5;
    int hp = blockIdx.x & 3;
    int i0 = (blockIdx.x >> 2) * MI;
    int hl = (w >= 6), mt = (w >= 6) ? w - 6 : w;
    int gid = lane >> 2, tig = lane & 3;
    int t2 = 2 * tig;
    int r0 = mt * 16 + gid;

    // per-row constants (rows r0 and r0+8, head hp*2+hl)
    int gi0 = (i0 + r0) * HH + hp * 2 + hl;
    int gi1 = gi0 + 8 * HH;
    float mA = d_m[gi0], mB = d_m[gi1];
    float slmA = d_sl[gi0] - mA, slmB = d_sl[gi1] - mB;
    float cmA = -0.8f * mA, cmB = -0.8f * mB;
    uint32_t CA2 = ph2(d_Cc[gi0], d_Cc[gi0]);
    uint32_t CB2 = ph2(d_Cc[gi1], d_Cc[gi1]);

    const uint32_t* ab0 = d_adjbits + (size_t)(i0 + r0) * NW;
    const uint32_t* ab1 = ab0 + 8 * NW;

    // ---- hoisted staging descriptors ----
    const char* g_src[3];
    uint32_t g_dst[3];
    int nit = (t < 256) ? 3 : 2;
    #pragma unroll
    for (int q = 0; q < 3; q++) {
        int idx = t + q * 384;
        if (idx < 1024) {
            int head = idx >> 9, rc = idx & 511;
            int f = rc >> 3, c = rc & 7;
            g_src[q] = (const char*)(d_gthi + ((size_t)(hp * 2 + head) * FF + f) * NN + c * 8);
            g_dst[q] = (uint32_t)(((head * 64 + f) * 80 + c * 8) * 2);
        }
    }
    const char* s_src = nullptr;
    uint32_t s_dst = 0;
    if (t < 128) {
        int head = t >> 6, p = t & 63;
        int joff = (p & ~15) + KTAB(p & 15);
        s_src = (const char*)(d_sr + (size_t)joff * HH + hp * 2 + head);
        s_dst = (uint32_t)((head * 64 + p) * 4);
    }

    auto stage = [&](int bi) {
        uint32_t boff = bi * BUF_BYTES;
        #pragma unroll
        for (int q = 0; q < 3; q++) {
            if (q < nit) {
                cp16(smem + boff + g_dst[q], g_src[q]);
                g_src[q] += 64 * 2;       // +64 j (halfs)
            }
        }
        if (t < 128) {
            cp4(smem + OFF_SR3 + bi * 512 + s_dst, s_src);
            s_src += 64 * HH * 4;         // +64 j (floats, stride HH)
        }
    };

    float d[8][4] = {};
    float dz[4] = {};
    uint32_t bz = (gid == 0) ? 0x3C003C00u : 0u;   // ones column (n=0)

    stage(0); CP_COMMIT();
    stage(1); CP_COMMIT();
    int cur = 0, stg = 2;

    for (int jt = 0; jt < NT; ++jt) {
        if (jt < NT - 1) CP_WAIT(1); else CP_WAIT(0);
        __syncthreads();
        if (jt + 2 < NT) { stage(stg); CP_COMMIT(); stg = (stg == 2) ? 0 : stg + 1; }

        uint2 bw0 = *(const uint2*)(ab0 + jt * 2);
        uint2 bw1 = *(const uint2*)(ab1 + jt * 2);
        const float* srh = (const float*)(smem + OFF_SR3 + cur * 512) + hl * 64;

        uint32_t A[4][4];
        #pragma unroll
        for (int s = 0; s < 4; s++) {
            float4 sv = *(const float4*)(srh + s * 16 + 4 * tig);
            uint32_t shA = ((s < 2) ? bw0.x : bw0.y) >> (((s & 1) << 4) + t2);
            uint32_t shB = ((s < 2) ? bw1.x : bw1.y) >> (((s & 1) << 4) + t2);
            // row r0: fp32 leaky, f16x2 exp, PRMT-LUT mask blend
            {
                float u0 = sv.x + slmA, u1 = sv.y + slmA;
                float u2 = sv.z + slmA, u3 = sv.w + slmA;
                float l0 = fmaxf(u0, fmaf(u0, 0.2f, cmA));
                float l1 = fmaxf(u1, fmaf(u1, 0.2f, cmA));
                float l2 = fmaxf(u2, fmaf(u2, 0.2f, cmA));
                float l3 = fmaxf(u3, fmaf(u3, 0.2f, cmA));
                uint32_t e01 = ex2h2(ph2(l0, l1));
                uint32_t e23 = ex2h2(ph2(l2, l3));
                uint32_t sel1 = (uint32_t)(SELLUT >> ((shA << 4) & 0x30));
                uint32_t sel2 = (uint32_t)(SELLUT >> ((shA >> 4) & 0x30));
                A[s][0] = __byte_perm(e01, CA2, sel1);
                A[s][2] = __byte_perm(e23, CA2, sel2);
            }
            // row r0+8
            {
                float u0 = sv.x + slmB, u1 = sv.y + slmB;
                float u2 = sv.z + slmB, u3 = sv.w + slmB;
                float l0 = fmaxf(u0, fmaf(u0, 0.2f, cmB));
                float l1 = fmaxf(u1, fmaf(u1, 0.2f, cmB));
                float l2 = fmaxf(u2, fmaf(u2, 0.2f, cmB));
                float l3 = fmaxf(u3, fmaf(u3, 0.2f, cmB));
                uint32_t e01 = ex2h2(ph2(l0, l1));
                uint32_t e23 = ex2h2(ph2(l2, l3));
                uint32_t sel1 = (uint32_t)(SELLUT >> ((shB << 4) & 0x30));
                uint32_t sel2 = (uint32_t)(SELLUT >> ((shB >> 4) & 0x30));
                A[s][1] = __byte_perm(e01, CB2, sel1);
                A[s][3] = __byte_perm(e23, CB2, sel2);
            }
            mma16816(dz, A[s], bz, bz);     // z accumulation on tensor pipe
        }

        const __half* bb = (const __half*)(smem + cur * BUF_BYTES) + hl * 64 * 80;
        #pragma unroll
        for (int s = 0; s < 4; s++) {
            #pragma unroll
            for (int nt = 0; nt < 8; nt++) {
                uint2 b = *(const uint2*)(bb + (nt * 8 + gid) * 80 + s * 16 + 4 * tig);
                mma16816(d[nt], A[s], b.x, b.y);
            }
        }
        cur = (cur == 2) ? 0 : cur + 1;
    }

    // ---- epilogue: z lives in dz[0]/dz[2] of tig==0 lanes ----
    float zA = __shfl_sync(0xffffffffu, dz[0], lane & ~3);
    float zB = __shfl_sync(0xffffffffu, dz[2], lane & ~3);
    float inv0 = 1.0f / zA;
    float inv1 = 1.0f / zB;
    int col0 = (hp * 2 + hl) * FF + 2 * tig;
    float* o0 = out + (size_t)(i0 + r0) * OUTF + col0;
    float* o1 = out + (size_t)(i0 + r0 + 8) * OUTF + col0;
    #pragma unroll
    for (int nt = 0; nt < 8; nt++) {
        *(float2*)(o0 + nt * 8) = make_float2(d[nt][0] * inv0, d[nt][1] * inv0);
        *(float2*)(o1 + nt * 8) = make_float2(d[nt][2] * inv1, d[nt][3] * inv1);
    }
}

// ============================================================
extern "C" void kernel_launch(void* const* d_in, const int* in_sizes, int n_in,
                              void* d_out, int out_size) {
    const float* x   = (const float*)d_in[0];
    const int*   adj = (const int*)d_in[1];
    const float* W   = (const float*)d_in[2];
    const float* aw  = (const float*)d_in[3];
    float* out = (float*)d_out;

    cudaFuncSetAttribute(gemm_tc, cudaFuncAttributeMaxDynamicSharedMemorySize, GEMM_SMEM);
    cudaFuncSetAttribute(gat_tc, cudaFuncAttributeMaxDynamicSharedMemorySize, SMEM_TC);

    prep_kernel<<<224, 256>>>(x, W);                          // launch 0
    gemm_tc<<<dim3(NN / 64, HH), 128, GEMM_SMEM>>>(aw);       // launch 1
    rowc_kernel<<<NN, 256>>>(adj);                            // launch 2
    gat_tc<<<(NN / MI) * 4, 384, SMEM_TC>>>(out);             // launch 3 (profiled)
}

// round 10
// speedup vs baseline: 6.5976x; 1.0025x over previous
#include <cuda_runtime.h>
#include <cuda_fp16.h>
#include <cstdint>

#define NN    3072
#define HH    8
#define FF    64
#define OUTF  512
#define INF_  256
#define KT    64
#define NT    (NN / KT)     // 48
#define MI    192           // i rows per CTA in gat_tc (one head per CTA)
#define NW    (NN / 32)     // adj bitmask words per row
#define LOG2E 1.4426950408889634f

// ---- scratch (device globals) ----
__device__ float d_sl[NN * HH];           // pre-scaled by log2(e)
__device__ float d_sr[NN * HH];           // pre-scaled
__device__ float d_m[NN * HH];            // scaled row max
__device__ float d_Cc[NN * HH];           // any0 ? exp2(LOG2E - m) : 0
__device__ uint32_t d_adjbits[NN * NW];
__device__ __half d_gthi[HH * FF * NN];   // g^T fp16 (rn), j-permuted: [h][f][j']
__device__ __half d_xphi[NN * INF_];      // x split hi, k-permuted
__device__ __half d_xplo[NN * INF_];
__device__ __half d_wthi[OUTF * INF_];    // W^T split hi, k-permuted: [n][k']
__device__ __half d_wtlo[OUTF * INF_];

// permutation within 16-group: position p holds actual k = KTAB(p)
#define KTAB(pp) (2 * ((pp) >> 2) + (((pp) & 2) ? 8 : 0) + ((pp) & 1))

// select LUT: 2 mask bits -> byte_perm selector (e bytes 0-3, C bytes 4-7)
static constexpr uint64_t SELLUT = 0x3210325476107654ull;

// ---------------- helpers ----------------
__device__ __forceinline__ uint32_t smem_u32(const void* p) {
    uint32_t a;
    asm("{ .reg .u64 t; cvta.to.shared.u64 t, %1; cvt.u32.u64 %0, t; }" : "=r"(a) : "l"(p));
    return a;
}
__device__ __forceinline__ void cp16(void* dst, const void* src) {
    asm volatile("cp.async.cg.shared.global [%0], [%1], 16;\n" :: "r"(smem_u32(dst)), "l"(src));
}
__device__ __forceinline__ void cp4(void* dst, const void* src) {
    asm volatile("cp.async.ca.shared.global [%0], [%1], 4;\n" :: "r"(smem_u32(dst)), "l"(src));
}
#define CP_COMMIT() asm volatile("cp.async.commit_group;\n")
#define CP_WAIT(n)  asm volatile("cp.async.wait_group %0;\n" :: "n"(n))

__device__ __forceinline__ void mma16816(float* d, const uint32_t* a,
                                         uint32_t b0, uint32_t b1) {
    asm volatile(
        "mma.sync.aligned.m16n8k16.row.col.f32.f16.f16.f32 "
        "{%0,%1,%2,%3}, {%4,%5,%6,%7}, {%8,%9}, {%0,%1,%2,%3};"
        : "+f"(d[0]), "+f"(d[1]), "+f"(d[2]), "+f"(d[3])
        : "r"(a[0]), "r"(a[1]), "r"(a[2]), "r"(a[3]), "r"(b0), "r"(b1));
}
__device__ __forceinline__ uint32_t ph2(float lo, float hi) {
    __half2 h = __floats2half2_rn(lo, hi);
    return *(uint32_t*)&h;
}
__device__ __forceinline__ uint32_t ex2h2(uint32_t a) {
    uint32_t r;
    asm("ex2.approx.f16x2 %0, %1;" : "=r"(r) : "r"(a));
    return r;
}
__device__ __forceinline__ void split16(const float* v_strided, int stride,
                                        uint4* hi2, uint4* lo2) {
    uint32_t hw[8], lw[8];
    #pragma unroll
    for (int q = 0; q < 8; q++) {
        float v0 = v_strided[KTAB(2 * q) * stride];
        float v1 = v_strided[KTAB(2 * q + 1) * stride];
        __half h0 = __float2half_rn(v0), h1 = __float2half_rn(v1);
        float r0 = v0 - __half2float(h0), r1 = v1 - __half2float(h1);
        __half l0 = __float2half_rn(r0), l1 = __float2half_rn(r1);
        hw[q] = ((uint32_t)__half_as_ushort(h1) << 16) | __half_as_ushort(h0);
        lw[q] = ((uint32_t)__half_as_ushort(l1) << 16) | __half_as_ushort(l0);
    }
    hi2[0] = make_uint4(hw[0], hw[1], hw[2], hw[3]);
    hi2[1] = make_uint4(hw[4], hw[5], hw[6], hw[7]);
    lo2[0] = make_uint4(lw[0], lw[1], lw[2], lw[3]);
    lo2[1] = make_uint4(lw[4], lw[5], lw[6], lw[7]);
}

// ============================================================
// Kernel 0: prep = xsplit (blocks 0..191) + wsplit (blocks 192..223)
// ============================================================
__global__ void prep_kernel(const float* __restrict__ x, const float* __restrict__ W) {
    int t = threadIdx.x;
    if (blockIdx.x < 192) {
        __shared__ float s[16][257];
        int r0 = blockIdx.x * 16;
        #pragma unroll
        for (int q = 0; q < 4; q++) {
            int idx = t + q * 256;
            int r = idx >> 6, c4 = (idx & 63) * 4;
            float4 v = *(const float4*)(x + (size_t)(r0 + r) * INF_ + c4);
            s[r][c4] = v.x; s[r][c4 + 1] = v.y; s[r][c4 + 2] = v.z; s[r][c4 + 3] = v.w;
        }
        __syncthreads();
        int r = t >> 4, grp = (t & 15) * 16;
        uint4 hi2[2], lo2[2];
        split16(&s[r][grp], 1, hi2, lo2);
        uint4* dh = (uint4*)(d_xphi + (size_t)(r0 + r) * INF_ + grp);
        uint4* dl = (uint4*)(d_xplo + (size_t)(r0 + r) * INF_ + grp);
        dh[0] = hi2[0]; dh[1] = hi2[1];
        dl[0] = lo2[0]; dl[1] = lo2[1];
    } else {
        __shared__ float s[64][65];
        int b = blockIdx.x - 192;
        int k0 = (b & 3) * 64, n0 = (b >> 2) * 64;
        #pragma unroll
        for (int q = 0; q < 4; q++) {
            int idx = t + q * 256;
            int k = idx >> 4, n4 = (idx & 15) * 4;
            float4 v = *(const float4*)(W + (size_t)(k0 + k) * OUTF + n0 + n4);
            s[k][n4] = v.x; s[k][n4 + 1] = v.y; s[k][n4 + 2] = v.z; s[k][n4 + 3] = v.w;
        }
        __syncthreads();
        int n = t >> 2, grp = (t & 3) * 16;
        uint4 hi2[2], lo2[2];
        split16(&s[grp][n], 65, hi2, lo2);
        uint4* dh = (uint4*)(d_wthi + (size_t)(n0 + n) * INF_ + k0 + grp);
        uint4* dl = (uint4*)(d_wtlo + (size_t)(n0 + n) * INF_ + k0 + grp);
        dh[0] = hi2[0]; dh[1] = hi2[1];
        dl[0] = lo2[0]; dl[1] = lo2[1];
    }
}

// ============================================================
// Kernel 1: g = x @ W via HMMA (3-pass split), fused epilogue:
// scores (scaled) + g^T fp16 j-permuted. grid (48, 8), 128 thr.
// ============================================================
constexpr int BROW = 264;
constexpr int GEMM_SMEM = 2 * 64 * BROW * 2;    // 67584 B

__global__ void __launch_bounds__(128, 1) gemm_tc(const float* __restrict__ aw) {
    extern __shared__ char gsm[];
    __half* Bhi = (__half*)gsm;
    __half* Blo = Bhi + 64 * BROW;
    int t = threadIdx.x, lane = t & 31, w = t >> 5;
    int m0 = blockIdx.x * 64, h = blockIdx.y, n0 = h * FF;

    #pragma unroll
    for (int q = 0; q < 16; q++) {
        int idx = t + q * 128;
        int n = idx >> 5, c = idx & 31;
        cp16(Bhi + n * BROW + c * 8, d_wthi + (size_t)(n0 + n) * INF_ + c * 8);
        cp16(Blo + n * BROW + c * 8, d_wtlo + (size_t)(n0 + n) * INF_ + c * 8);
    }
    CP_COMMIT(); CP_WAIT(0);
    __syncthreads();

    int gid = lane >> 2, tig = lane & 3;
    const uint2* xh0 = (const uint2*)(d_xphi + (size_t)(m0 + w * 16 + gid) * INF_);
    const uint2* xh8 = (const uint2*)(d_xphi + (size_t)(m0 + w * 16 + gid + 8) * INF_);
    const uint2* xl0 = (const uint2*)(d_xplo + (size_t)(m0 + w * 16 + gid) * INF_);
    const uint2* xl8 = (const uint2*)(d_xplo + (size_t)(m0 + w * 16 + gid + 8) * INF_);

    float d[8][4] = {};
    #pragma unroll 4
    for (int s = 0; s < 16; s++) {
        uint2 ah0 = xh0[s * 4 + tig], ah8 = xh8[s * 4 + tig];
        uint2 al0 = xl0[s * 4 + tig], al8 = xl8[s * 4 + tig];
        uint32_t Ahi[4] = {ah0.x, ah8.x, ah0.y, ah8.y};
        uint32_t Alo[4] = {al0.x, al8.x, al0.y, al8.y};
        #pragma unroll
        for (int nt = 0; nt < 8; nt++) {
            int boff = (nt * 8 + gid) * BROW + s * 16 + 4 * tig;
            uint2 bh = *(const uint2*)(Bhi + boff);
            uint2 bl = *(const uint2*)(Blo + boff);
            mma16816(d[nt], Ahi, bh.x, bh.y);
            mma16816(d[nt], Ahi, bl.x, bl.y);
            mma16816(d[nt], Alo, bh.x, bh.y);
        }
    }
    __syncthreads();    // B dead; overlay transpose buffer

    float* trans = (float*)gsm;     // [64][66]
    int r1 = w * 16 + gid, r2 = r1 + 8;
    #pragma unroll
    for (int nt = 0; nt < 8; nt++) {
        int cc = nt * 8 + 2 * tig;
        trans[r1 * 66 + cc] = d[nt][0]; trans[r1 * 66 + cc + 1] = d[nt][1];
        trans[r2 * 66 + cc] = d[nt][2]; trans[r2 * 66 + cc + 1] = d[nt][3];
    }
    __syncthreads();

    // ---- fused scores (x log2e) ----
    {
        int r = t >> 1, half = t & 1;
        const float* row = trans + r * 66 + half * 32;
        const float* awl = aw + half * 32;
        const float* awr = aw + 64 + half * 32;
        float sl = 0.f, sr = 0.f;
        #pragma unroll
        for (int q = 0; q < 32; q++) {
            float gv = row[q];
            sl += gv * awl[q];
            sr += gv * awr[q];
        }
        sl += __shfl_xor_sync(0xffffffffu, sl, 1);
        sr += __shfl_xor_sync(0xffffffffu, sr, 1);
        if (!half) {
            d_sl[(m0 + r) * HH + h] = sl * LOG2E;
            d_sr[(m0 + r) * HH + h] = sr * LOG2E;
        }
    }

    // ---- g^T fp16 (hi only), j-permuted ----
    {
        int f = t >> 1, half = t & 1;
        #pragma unroll
        for (int jq = 0; jq < 2; jq++) {
            int p0 = 32 * half + jq * 16;
            uint32_t hw[8];
            #pragma unroll
            for (int q = 0; q < 8; q++) {
                float v0 = trans[(p0 + KTAB(2 * q)) * 66 + f];
                float v1 = trans[(p0 + KTAB(2 * q + 1)) * 66 + f];
                hw[q] = ph2(v0, v1);
            }
            uint4* dh = (uint4*)(d_gthi + ((size_t)h * FF + f) * NN + m0 + p0);
            dh[0] = make_uint4(hw[0], hw[1], hw[2], hw[3]);
            dh[1] = make_uint4(hw[4], hw[5], hw[6], hw[7]);
        }
    }
}

// ============================================================
// Kernel 2: per-row adj scan -> m[i,h] (scaled), C; packs adj bits
// ============================================================
__global__ void rowc_kernel(const int* __restrict__ adj) {
    int i = blockIdx.x, t = threadIdx.x;
    float mx[8];
    #pragma unroll
    for (int h = 0; h < 8; h++) mx[h] = -3.0e38f;
    int any0 = 0;
    const int* ar = adj + (size_t)i * NN;
    for (int j = t; j < NN; j += 256) {
        int a = ar[j];
        uint32_t bal = __ballot_sync(0xffffffffu, a != 0);
        if ((t & 31) == 0) d_adjbits[i * NW + (j >> 5)] = bal;
        if (a) {
            const float4* p = (const float4*)(d_sr + j * HH);
            float4 v0 = p[0], v1 = p[1];
            mx[0] = fmaxf(mx[0], v0.x); mx[1] = fmaxf(mx[1], v0.y);
            mx[2] = fmaxf(mx[2], v0.z); mx[3] = fmaxf(mx[3], v0.w);
            mx[4] = fmaxf(mx[4], v1.x); mx[5] = fmaxf(mx[5], v1.y);
            mx[6] = fmaxf(mx[6], v1.z); mx[7] = fmaxf(mx[7], v1.w);
        } else any0 = 1;
    }
    __shared__ float wmax[8][8];
    __shared__ int s_any;
    if (t == 0) s_any = 0;
    __syncthreads();
    if (any0) s_any = 1;
    int lane = t & 31, wid = t >> 5;
    #pragma unroll
    for (int h = 0; h < 8; h++) {
        float v = mx[h];
        #pragma unroll
        for (int o = 16; o; o >>= 1) v = fmaxf(v, __shfl_down_sync(0xffffffffu, v, o));
        if (lane == 0) wmax[h][wid] = v;
    }
    __syncthreads();
    if (t < 8) {
        int h = t;
        float mradj = wmax[h][0];
        #pragma unroll
        for (int w = 1; w < 8; w++) mradj = fmaxf(mradj, wmax[h][w]);
        float sl = d_sl[i * HH + h];
        float s  = sl + mradj;
        float lk = fmaxf(s, 0.2f * s);
        float m  = s_any ? fmaxf(LOG2E, lk) : lk;
        d_m[i * HH + h]  = m;
        d_Cc[i * HH + h] = s_any ? exp2f(LOG2E - m) : 0.0f;
    }
}

// ============================================================
// Kernel 3: HMMA main. ONE HEAD PER CTA (B tile shared by all 12 warps).
// grid 128 = 16 i-tiles(192) x 8 heads, 384 thr, smem 31KB.
// ============================================================
constexpr int BUF_BYTES = 64 * 80 * 2;              // 10240 per stage
constexpr int OFF_SR3   = 3 * BUF_BYTES;            // 30720
constexpr int SMEM_TC   = OFF_SR3 + 3 * 256;        // 31488

__global__ void __launch_bounds__(384, 1) gat_tc(float* __restrict__ out) {
    extern __shared__ char smem[];

    int t = threadIdx.x, lane = t & 31, mt = t >> 5;
    int h = blockIdx.x & 7;
    int i0 = (blockIdx.x >> 3) * MI;
    int gid = lane >> 2, tig = lane & 3;
    int t2 = 2 * tig;
    int r0 = mt * 16 + gid;             // rows r0, r0+8 of this CTA's 192

    // per-row constants
    int gi0 = (i0 + r0) * HH + h;
    int gi1 = gi0 + 8 * HH;
    float mA = d_m[gi0], mB = d_m[gi1];
    float slmA = d_sl[gi0] - mA, slmB = d_sl[gi1] - mB;
    float cmA = -0.8f * mA, cmB = -0.8f * mB;
    uint32_t CA2 = ph2(d_Cc[gi0], d_Cc[gi0]);
    uint32_t CB2 = ph2(d_Cc[gi1], d_Cc[gi1]);

    const uint32_t* ab0 = d_adjbits + (size_t)(i0 + r0) * NW;
    const uint32_t* ab1 = ab0 + 8 * NW;

    // ---- hoisted staging descriptors (512 cp16 over 384 threads) ----
    const char* g_src[2];
    uint32_t g_dst[2];
    int nit = (t < 128) ? 2 : 1;
    #pragma unroll
    for (int q = 0; q < 2; q++) {
        int idx = t + q * 384;
        if (idx < 512) {
            int f = idx >> 3, c = idx & 7;
            g_src[q] = (const char*)(d_gthi + ((size_t)h * FF + f) * NN + c * 8);
            g_dst[q] = (uint32_t)((f * 80 + c * 8) * 2);
        }
    }
    const char* s_src = nullptr;
    uint32_t s_dst = 0;
    if (t < 64) {
        int joff = (t & ~15) + KTAB(t & 15);
        s_src = (const char*)(d_sr + (size_t)joff * HH + h);
        s_dst = (uint32_t)(t * 4);
    }

    auto stage = [&](int bi) {
        uint32_t boff = bi * BUF_BYTES;
        #pragma unroll
        for (int q = 0; q < 2; q++) {
            if (q < nit) {
                cp16(smem + boff + g_dst[q], g_src[q]);
                g_src[q] += 64 * 2;       // +64 j (halfs)
            }
        }
        if (t < 64) {
            cp4(smem + OFF_SR3 + bi * 256 + s_dst, s_src);
            s_src += 64 * HH * 4;         // +64 j (floats, stride HH)
        }
    };

    float d[8][4] = {};
    float dz[4] = {};
    uint32_t bz = (gid == 0) ? 0x3C003C00u : 0u;   // ones column (n=0)

    stage(0); CP_COMMIT();
    stage(1); CP_COMMIT();
    int cur = 0, stg = 2;

    for (int jt = 0; jt < NT; ++jt) {
        if (jt < NT - 1) CP_WAIT(1); else CP_WAIT(0);
        __syncthreads();
        if (jt + 2 < NT) { stage(stg); CP_COMMIT(); stg = (stg == 2) ? 0 : stg + 1; }

        uint2 bw0 = *(const uint2*)(ab0 + jt * 2);
        uint2 bw1 = *(const uint2*)(ab1 + jt * 2);
        const float* srh = (const float*)(smem + OFF_SR3 + cur * 256);

        uint32_t A[4][4];
        #pragma unroll
        for (int s = 0; s < 4; s++) {
            float4 sv = *(const float4*)(srh + s * 16 + 4 * tig);
            uint32_t shA = ((s < 2) ? bw0.x : bw0.y) >> (((s & 1) << 4) + t2);
            uint32_t shB = ((s < 2) ? bw1.x : bw1.y) >> (((s & 1) << 4) + t2);
            // row r0
            {
                float u0 = sv.x + slmA, u1 = sv.y + slmA;
                float u2 = sv.z + slmA, u3 = sv.w + slmA;
                float l0 = fmaxf(u0, fmaf(u0, 0.2f, cmA));
                float l1 = fmaxf(u1, fmaf(u1, 0.2f, cmA));
                float l2 = fmaxf(u2, fmaf(u2, 0.2f, cmA));
                float l3 = fmaxf(u3, fmaf(u3, 0.2f, cmA));
                uint32_t e01 = ex2h2(ph2(l0, l1));
                uint32_t e23 = ex2h2(ph2(l2, l3));
                uint32_t sel1 = (uint32_t)(SELLUT >> ((shA << 4) & 0x30));
                uint32_t sel2 = (uint32_t)(SELLUT >> ((shA >> 4) & 0x30));
                A[s][0] = __byte_perm(e01, CA2, sel1);
                A[s][2] = __byte_perm(e23, CA2, sel2);
            }
            // row r0+8
            {
                float u0 = sv.x + slmB, u1 = sv.y + slmB;
                float u2 = sv.z + slmB, u3 = sv.w + slmB;
                float l0 = fmaxf(u0, fmaf(u0, 0.2f, cmB));
                float l1 = fmaxf(u1, fmaf(u1, 0.2f, cmB));
                float l2 = fmaxf(u2, fmaf(u2, 0.2f, cmB));
                float l3 = fmaxf(u3, fmaf(u3, 0.2f, cmB));
                uint32_t e01 = ex2h2(ph2(l0, l1));
                uint32_t e23 = ex2h2(ph2(l2, l3));
                uint32_t sel1 = (uint32_t)(SELLUT >> ((shB << 4) & 0x30));
                uint32_t sel2 = (uint32_t)(SELLUT >> ((shB >> 4) & 0x30));
                A[s][1] = __byte_perm(e01, CB2, sel1);
                A[s][3] = __byte_perm(e23, CB2, sel2);
            }
            mma16816(dz, A[s], bz, bz);     // z accumulation on tensor pipe
        }

        const __half* bb = (const __half*)(smem + cur * BUF_BYTES);
        #pragma unroll
        for (int s = 0; s < 4; s++) {
            #pragma unroll
            for (int nt = 0; nt < 8; nt++) {
                uint2 b = *(const uint2*)(bb + (nt * 8 + gid) * 80 + s * 16 + 4 * tig);
                mma16816(d[nt], A[s], b.x, b.y);
            }
        }
        cur = (cur == 2) ? 0 : cur + 1;
    }

    // ---- epilogue: z lives in dz[0]/dz[2] of tig==0 lanes ----
    float zA = __shfl_sync(0xffffffffu, dz[0], lane & ~3);
    float zB = __shfl_sync(0xffffffffu, dz[2], lane & ~3);
    float inv0 = 1.0f / zA;
    float inv1 = 1.0f / zB;
    int col0 = h * FF + 2 * tig;
    float* o0 = out + (size_t)(i0 + r0) * OUTF + col0;
    float* o1 = out + (size_t)(i0 + r0 + 8) * OUTF + col0;
    #pragma unroll
    for (int nt = 0; nt < 8; nt++) {
        *(float2*)(o0 + nt * 8) = make_float2(d[nt][0] * inv0, d[nt][1] * inv0);
        *(float2*)(o1 + nt * 8) = make_float2(d[nt][2] * inv1, d[nt][3] * inv1);
    }
}

// ============================================================
extern "C" void kernel_launch(void* const* d_in, const int* in_sizes, int n_in,
                              void* d_out, int out_size) {
    const float* x   = (const float*)d_in[0];
    const int*   adj = (const int*)d_in[1];
    const float* W   = (const float*)d_in[2];
    const float* aw  = (const float*)d_in[3];
    float* out = (float*)d_out;

    cudaFuncSetAttribute(gemm_tc, cudaFuncAttributeMaxDynamicSharedMemorySize, GEMM_SMEM);
    cudaFuncSetAttribute(gat_tc, cudaFuncAttributeMaxDynamicSharedMemorySize, SMEM_TC);

    prep_kernel<<<224, 256>>>(x, W);                          // launch 0
    gemm_tc<<<dim3(NN / 64, HH), 128, GEMM_SMEM>>>(aw);       // launch 1
    rowc_kernel<<<NN, 256>>>(adj);                            // launch 2
    gat_tc<<<(NN / MI) * HH, 384, SMEM_TC>>>(out);            // launch 3 (profiled)
}